// round 2
// baseline (speedup 1.0000x reference)
#include <cuda_runtime.h>
#include <float.h>
#include <math.h>

// Problem dims
#define Bn 2
#define Sn 2048
#define Hn 16
#define Dn 64
#define En 1024
#define M_ROWS (Bn*Sn)                 // 4096
#define QSZ ((size_t)Bn*Hn*Sn*Dn)      // 4,194,304
#define WSZ ((size_t)Bn*Hn*Sn*Sn)      // 134,217,728

// Scratch: Q1,K1,V1,Q2,K2,V2,C1,C2,PACK  (9 x 16 MB)
__device__ float g_scratch[9 * 4194304];

// ---------------------------------------------------------------------------
// Projection GEMM: Y[b,h,s,d] = sum_e X[b,s,e] * W[f,e],  f = h*64+d
// A = X (4096 x 1024) row-major, B = W (1024 x 1024) row-major, C = A @ B^T
// 64x64 tile, BK=16, 256 threads, 4x4 per thread.
// ---------------------------------------------------------------------------
__global__ void proj_gemm(const float* __restrict__ X, const float* __restrict__ W,
                          float* __restrict__ Y) {
    __shared__ float As[64][17];
    __shared__ float Bs[64][17];
    const int tx = threadIdx.x;
    const int tr = tx >> 4, tc = tx & 15;
    const int row0 = blockIdx.y * 64, col0 = blockIdx.x * 64;
    const int li = tx >> 2;           // 0..63
    const int lk = (tx & 3) * 4;      // 0,4,8,12
    float acc[4][4] = {};

    for (int kk = 0; kk < En; kk += 16) {
        float4 xa = *(const float4*)&X[(size_t)(row0 + li) * En + kk + lk];
        float4 wb = *(const float4*)&W[(size_t)(col0 + li) * En + kk + lk];
        As[li][lk + 0] = xa.x; As[li][lk + 1] = xa.y; As[li][lk + 2] = xa.z; As[li][lk + 3] = xa.w;
        Bs[li][lk + 0] = wb.x; Bs[li][lk + 1] = wb.y; Bs[li][lk + 2] = wb.z; Bs[li][lk + 3] = wb.w;
        __syncthreads();
        #pragma unroll
        for (int k = 0; k < 16; k++) {
            float a[4], b[4];
            #pragma unroll
            for (int r = 0; r < 4; r++) a[r] = As[tr * 4 + r][k];
            #pragma unroll
            for (int c = 0; c < 4; c++) b[c] = Bs[tc * 4 + c][k];
            #pragma unroll
            for (int r = 0; r < 4; r++)
                #pragma unroll
                for (int c = 0; c < 4; c++) acc[r][c] += a[r] * b[c];
        }
        __syncthreads();
    }
    #pragma unroll
    for (int r = 0; r < 4; r++) {
        const int m = row0 + tr * 4 + r;
        const int b = m >> 11, s = m & (Sn - 1);
        #pragma unroll
        for (int c = 0; c < 4; c++) {
            const int f = col0 + tc * 4 + c;
            const int h = f >> 6, d = f & 63;
            Y[(((size_t)(b * Hn + h)) * Sn + s) * Dn + d] = acc[r][c];
        }
    }
}

// ---------------------------------------------------------------------------
// Output GEMM: plain row-major output  out[m, n] = sum_e X[m,e] * W[n,e]
// ---------------------------------------------------------------------------
__global__ void out_gemm(const float* __restrict__ X, const float* __restrict__ W,
                         float* __restrict__ Y) {
    __shared__ float As[64][17];
    __shared__ float Bs[64][17];
    const int tx = threadIdx.x;
    const int tr = tx >> 4, tc = tx & 15;
    const int row0 = blockIdx.y * 64, col0 = blockIdx.x * 64;
    const int li = tx >> 2;
    const int lk = (tx & 3) * 4;
    float acc[4][4] = {};

    for (int kk = 0; kk < En; kk += 16) {
        float4 xa = *(const float4*)&X[(size_t)(row0 + li) * En + kk + lk];
        float4 wb = *(const float4*)&W[(size_t)(col0 + li) * En + kk + lk];
        As[li][lk + 0] = xa.x; As[li][lk + 1] = xa.y; As[li][lk + 2] = xa.z; As[li][lk + 3] = xa.w;
        Bs[li][lk + 0] = wb.x; Bs[li][lk + 1] = wb.y; Bs[li][lk + 2] = wb.z; Bs[li][lk + 3] = wb.w;
        __syncthreads();
        #pragma unroll
        for (int k = 0; k < 16; k++) {
            float a[4], b[4];
            #pragma unroll
            for (int r = 0; r < 4; r++) a[r] = As[tr * 4 + r][k];
            #pragma unroll
            for (int c = 0; c < 4; c++) b[c] = Bs[tc * 4 + c][k];
            #pragma unroll
            for (int r = 0; r < 4; r++)
                #pragma unroll
                for (int c = 0; c < 4; c++) acc[r][c] += a[r] * b[c];
        }
        __syncthreads();
    }
    #pragma unroll
    for (int r = 0; r < 4; r++)
        #pragma unroll
        for (int c = 0; c < 4; c++)
            Y[(size_t)(row0 + tr * 4 + r) * En + col0 + tc * 4 + c] = acc[r][c];
}

// ---------------------------------------------------------------------------
// RoPE in place on [B,H,S,64] tensor. half = 32.
// ---------------------------------------------------------------------------
__global__ void rope_kernel(float* __restrict__ X) {
    const int idx = blockIdx.x * 256 + threadIdx.x;
    if (idx >= Bn * Hn * Sn * 32) return;
    const int j = idx & 31;
    const int row = idx >> 5;
    const int s = row & (Sn - 1);
    const double inv_d = pow(10000.0, -(double)j / 32.0);
    const float ang = (float)((double)s * inv_d);
    const float sv = sinf(ang), cv = cosf(ang);
    float* p = X + (size_t)row * Dn;
    const float x1 = p[j], x2 = p[j + 32];
    p[j]      = x1 * cv - x2 * sv;
    p[j + 32] = x1 * sv + x2 * cv;
}

// ---------------------------------------------------------------------------
// Scores: Wout[bh, q, k] = scale * sum_d Q[bh,q,d] * K[bh,k,d]
// grid (kTile=32, qTile=32, bh=32); strictly-upper tiles skipped (causal).
// ---------------------------------------------------------------------------
__global__ void scores_gemm(const float* __restrict__ Q, const float* __restrict__ K,
                            float* __restrict__ Wout) {
    if (blockIdx.x > blockIdx.y) return;   // whole tile masked
    const int bh = blockIdx.z;
    const float* Qb = Q + (size_t)bh * Sn * Dn;
    const float* Kb = K + (size_t)bh * Sn * Dn;
    __shared__ float As[64][17];
    __shared__ float Bs[64][17];
    const int tx = threadIdx.x;
    const int tr = tx >> 4, tc = tx & 15;
    const int q0 = blockIdx.y * 64, k0 = blockIdx.x * 64;
    const int li = tx >> 2;
    const int lk = (tx & 3) * 4;
    float acc[4][4] = {};

    for (int kk = 0; kk < Dn; kk += 16) {
        float4 qa = *(const float4*)&Qb[(size_t)(q0 + li) * Dn + kk + lk];
        float4 kb = *(const float4*)&Kb[(size_t)(k0 + li) * Dn + kk + lk];
        As[li][lk + 0] = qa.x; As[li][lk + 1] = qa.y; As[li][lk + 2] = qa.z; As[li][lk + 3] = qa.w;
        Bs[li][lk + 0] = kb.x; Bs[li][lk + 1] = kb.y; Bs[li][lk + 2] = kb.z; Bs[li][lk + 3] = kb.w;
        __syncthreads();
        #pragma unroll
        for (int k = 0; k < 16; k++) {
            float a[4], b[4];
            #pragma unroll
            for (int r = 0; r < 4; r++) a[r] = As[tr * 4 + r][k];
            #pragma unroll
            for (int c = 0; c < 4; c++) b[c] = Bs[tc * 4 + c][k];
            #pragma unroll
            for (int r = 0; r < 4; r++)
                #pragma unroll
                for (int c = 0; c < 4; c++) acc[r][c] += a[r] * b[c];
        }
        __syncthreads();
    }
    const float scale = 0.125f;  // 1/sqrt(64)
    #pragma unroll
    for (int r = 0; r < 4; r++)
        #pragma unroll
        for (int c = 0; c < 4; c++)
            Wout[((size_t)bh * Sn + q0 + tr * 4 + r) * Sn + k0 + tc * 4 + c] = acc[r][c] * scale;
}

// ---------------------------------------------------------------------------
// In-place causal softmax over rows of W (length 2048, valid prefix q+1).
// One block (256 threads) per row. Writes zeros in masked region.
// ---------------------------------------------------------------------------
__global__ void softmax_kernel(float* __restrict__ Wm) {
    const int row = blockIdx.x;            // bh*Sn + q
    const int q = row & (Sn - 1);
    float* p = Wm + (size_t)row * Sn;
    const int n = q + 1;
    const int tid = threadIdx.x;
    __shared__ float smax[8];
    __shared__ float ssum[8];

    float m = -FLT_MAX;
    for (int k = tid; k < n; k += 256) m = fmaxf(m, p[k]);
    #pragma unroll
    for (int o = 16; o; o >>= 1) m = fmaxf(m, __shfl_xor_sync(0xffffffffu, m, o));
    if ((tid & 31) == 0) smax[tid >> 5] = m;
    __syncthreads();
    if (tid == 0) {
        float mm = smax[0];
        #pragma unroll
        for (int i = 1; i < 8; i++) mm = fmaxf(mm, smax[i]);
        smax[0] = mm;
    }
    __syncthreads();
    m = smax[0];

    float sum = 0.f;
    for (int k = tid; k < n; k += 256) sum += expf(p[k] - m);
    #pragma unroll
    for (int o = 16; o; o >>= 1) sum += __shfl_xor_sync(0xffffffffu, sum, o);
    if ((tid & 31) == 0) ssum[tid >> 5] = sum;
    __syncthreads();
    if (tid == 0) {
        float s = 0.f;
        #pragma unroll
        for (int i = 0; i < 8; i++) s += ssum[i];
        ssum[0] = s;
    }
    __syncthreads();
    const float inv = 1.0f / ssum[0];

    for (int k = tid; k < n; k += 256) p[k] = expf(p[k] - m) * inv;
    for (int k = n + tid; k < Sn; k += 256) p[k] = 0.f;
}

// ---------------------------------------------------------------------------
// ctx[bh, q, d] = sum_k W[bh,q,k] * V[bh,k,d], causal (k-tiles <= q-tile only)
// grid (1, qTile=32, bh=32)
// ---------------------------------------------------------------------------
__global__ void ctx_gemm(const float* __restrict__ Wm, const float* __restrict__ V,
                         float* __restrict__ C) {
    const int bh = blockIdx.z;
    const int q0 = blockIdx.y * 64;
    const float* Wb = Wm + (size_t)bh * Sn * Sn;
    const float* Vb = V + (size_t)bh * Sn * Dn;
    __shared__ float As[64][17];   // w tile: 64 q x 16 k
    __shared__ float Bs[16][64];   // v tile: 16 k x 64 d
    const int tx = threadIdx.x;
    const int tr = tx >> 4, tc = tx & 15;
    const int li = tx >> 2;
    const int lk = (tx & 3) * 4;
    const int vi = tx >> 4;          // 0..15
    const int vk = (tx & 15) * 4;    // 0..60
    float acc[4][4] = {};
    const int kmax = q0 + 64;        // exclusive; covers all valid k for this q tile

    for (int kk = 0; kk < kmax; kk += 16) {
        float4 wa = *(const float4*)&Wb[(size_t)(q0 + li) * Sn + kk + lk];
        float4 vv = *(const float4*)&Vb[(size_t)(kk + vi) * Dn + vk];
        As[li][lk + 0] = wa.x; As[li][lk + 1] = wa.y; As[li][lk + 2] = wa.z; As[li][lk + 3] = wa.w;
        Bs[vi][vk + 0] = vv.x; Bs[vi][vk + 1] = vv.y; Bs[vi][vk + 2] = vv.z; Bs[vi][vk + 3] = vv.w;
        __syncthreads();
        #pragma unroll
        for (int k = 0; k < 16; k++) {
            float a[4], b[4];
            #pragma unroll
            for (int r = 0; r < 4; r++) a[r] = As[tr * 4 + r][k];
            #pragma unroll
            for (int c = 0; c < 4; c++) b[c] = Bs[k][tc * 4 + c];
            #pragma unroll
            for (int r = 0; r < 4; r++)
                #pragma unroll
                for (int c = 0; c < 4; c++) acc[r][c] += a[r] * b[c];
        }
        __syncthreads();
    }
    #pragma unroll
    for (int r = 0; r < 4; r++)
        #pragma unroll
        for (int c = 0; c < 4; c++)
            C[((size_t)bh * Sn + q0 + tr * 4 + r) * Dn + tc * 4 + c] = acc[r][c];
}

// ctx1 *= ctx2
__global__ void mul_kernel(float* __restrict__ a, const float* __restrict__ b) {
    const size_t i = (size_t)blockIdx.x * 256 + threadIdx.x;
    if (i < QSZ) a[i] *= b[i];
}

// pack [b,h,s,d] -> [b,s,h*64+d]
__global__ void pack_kernel(const float* __restrict__ C, float* __restrict__ P) {
    const size_t i = (size_t)blockIdx.x * 256 + threadIdx.x;
    if (i >= QSZ) return;
    const int d = (int)(i & 63);
    const size_t r = i >> 6;
    const int s = (int)(r & (Sn - 1));
    const size_t r2 = r >> 11;
    const int h = (int)(r2 & (Hn - 1));
    const int b = (int)(r2 >> 4);
    P[((size_t)(b * Sn + s)) * En + h * Dn + d] = C[i];
}

// ---------------------------------------------------------------------------
extern "C" void kernel_launch(void* const* d_in, const int* in_sizes, int n_in,
                              void* d_out, int out_size) {
    const float* query = (const float*)d_in[0];
    const float* key   = (const float*)d_in[1];
    const float* value = (const float*)d_in[2];
    // d_in[3] = mask: causal tril, hardcoded — not read.
    const float* WQ1 = (const float*)d_in[4];
    const float* WK1 = (const float*)d_in[5];
    const float* WV1 = (const float*)d_in[6];
    const float* WQ2 = (const float*)d_in[7];
    const float* WK2 = (const float*)d_in[8];
    const float* WV2 = (const float*)d_in[9];
    const float* WO  = (const float*)d_in[10];

    float* out = (float*)d_out;
    float* w1  = out + (size_t)M_ROWS * En;   // after out (4,194,304 floats)
    float* w2  = w1 + WSZ;

    float* sc = nullptr;
    cudaGetSymbolAddress((void**)&sc, g_scratch);
    float* Q1 = sc + 0 * QSZ;
    float* K1 = sc + 1 * QSZ;
    float* V1 = sc + 2 * QSZ;
    float* Q2 = sc + 3 * QSZ;
    float* K2 = sc + 4 * QSZ;
    float* V2 = sc + 5 * QSZ;
    float* C1 = sc + 6 * QSZ;
    float* C2 = sc + 7 * QSZ;
    float* PK = sc + 8 * QSZ;

    const dim3 gp(En / 64, M_ROWS / 64);   // (16, 64)

    proj_gemm<<<gp, 256>>>(query, WQ1, Q1);
    proj_gemm<<<gp, 256>>>(key,   WK1, K1);
    proj_gemm<<<gp, 256>>>(value, WV1, V1);
    proj_gemm<<<gp, 256>>>(query, WQ2, Q2);
    proj_gemm<<<gp, 256>>>(key,   WK2, K2);
    proj_gemm<<<gp, 256>>>(value, WV2, V2);

    const int rope_elems = Bn * Hn * Sn * 32;
    rope_kernel<<<rope_elems / 256, 256>>>(Q1);
    rope_kernel<<<rope_elems / 256, 256>>>(K1);
    rope_kernel<<<rope_elems / 256, 256>>>(Q2);
    rope_kernel<<<rope_elems / 256, 256>>>(K2);

    scores_gemm<<<dim3(32, 32, Bn * Hn), 256>>>(Q1, K1, w1);
    scores_gemm<<<dim3(32, 32, Bn * Hn), 256>>>(Q2, K2, w2);

    softmax_kernel<<<Bn * Hn * Sn, 256>>>(w1);
    softmax_kernel<<<Bn * Hn * Sn, 256>>>(w2);

    ctx_gemm<<<dim3(1, 32, Bn * Hn), 256>>>(w1, V1, C1);
    ctx_gemm<<<dim3(1, 32, Bn * Hn), 256>>>(w2, V2, C2);

    mul_kernel<<<(int)((QSZ + 255) / 256), 256>>>(C1, C2);
    pack_kernel<<<(int)((QSZ + 255) / 256), 256>>>(C1, PK);

    out_gemm<<<gp, 256>>>(PK, WO, out);
}

// round 4
// speedup vs baseline: 1.4659x; 1.4659x over previous
#include <cuda_runtime.h>
#include <cuda_bf16.h>
#include <cstdint>
#include <float.h>
#include <math.h>

#define Bn 2
#define Sn 2048
#define Hn 16
#define Dn 64
#define En 1024
#define M_ROWS (Bn*Sn)
#define QSZ ((size_t)Bn*Hn*Sn*Dn)
#define WSZ ((size_t)Bn*Hn*Sn*Sn)
#define MBb (1024ull*1024ull)

// ---- scratch layout (MB offsets) ----
// XQ 0, XK 16, XV 32, WC[7] 48+4i, Y[6] 76+16i, QS[4] 172+16i, VT[2] 236+16i,
// WP 268 (512MB), CC[2] 780+16i, PP 812
__device__ __align__(1024) unsigned char g_scratch[868220928];

__device__ __forceinline__ void split2(float a, __nv_bfloat16& h, __nv_bfloat16& l) {
    h = __float2bfloat16(a);
    l = __float2bfloat16(a - __bfloat162float(h));
}

// ============================================================================
// bf16 mma.sync GEMM:  C[m,n] = scale * sum_k A[m,k]*B[n,k]
// A: [M x 2K] bf16 rows [hi | lo], B: [N x 2K] bf16 rows [hi | lo].
// 3 passes: hi*hi, hi*lo, lo*hi (accumulated in registers, fp32).
// BM=128, BK=64 per chunk. mode: 0 none, 1 causal tile-skip, 2 causal kmax.
// ============================================================================
template<int BN, int WR, int WCn>
__global__ void __launch_bounds__(256) gemm_mma(
    const __nv_bfloat16* __restrict__ A, const __nv_bfloat16* __restrict__ B,
    float* __restrict__ C,
    long long sAz, long long sBz, long long sCz,
    int lda, int ldb, int ldc, int Kblk, float scale, int mode)
{
    constexpr int BM = 128, STR = 72;
    constexpr int THREADS = WR * WCn * 32;
    constexpr int WM = BM / WR, WN = BN / WCn;
    constexpr int MF = WM / 16, NF = WN / 8;
    constexpr int ALD = BM * 64 / 8 / THREADS;
    constexpr int BLD = BN * 64 / 8 / THREADS;

    const int m0 = blockIdx.y * BM;
    const int n0 = blockIdx.x * BN;
    if (mode == 1 && n0 > m0 + BM - 1) return;
    const int kmax = (mode == 2) ? min(Kblk, m0 + BM) : Kblk;
    const int nk = kmax >> 6;
    const int nch = nk * 3;

    A += (size_t)blockIdx.z * sAz;
    B += (size_t)blockIdx.z * sBz;
    C += (size_t)blockIdx.z * sCz;

    __shared__ __nv_bfloat16 Asm[BM * STR];
    __shared__ __nv_bfloat16 Bsm[BN * STR];

    const int tid = threadIdx.x;
    const int lane = tid & 31;
    const int w = tid >> 5;
    const int wm = (w / WCn) * WM;
    const int wn = (w % WCn) * WN;

    float acc[MF][NF][4] = {};
    uint4 ra[ALD], rb[BLD];

    auto loadc = [&](int t) {
        const int p = t / nk, kc = t % nk;
        const __nv_bfloat16* Ab = A + ((p == 2) ? Kblk : 0) + kc * 64;
        const __nv_bfloat16* Bb = B + ((p == 1) ? Kblk : 0) + kc * 64;
        #pragma unroll
        for (int i = 0; i < ALD; i++) {
            const int u = i * THREADS + tid;
            ra[i] = *(const uint4*)(Ab + (size_t)(m0 + (u >> 3)) * lda + (u & 7) * 8);
        }
        #pragma unroll
        for (int i = 0; i < BLD; i++) {
            const int u = i * THREADS + tid;
            rb[i] = *(const uint4*)(Bb + (size_t)(n0 + (u >> 3)) * ldb + (u & 7) * 8);
        }
    };

    loadc(0);
    for (int t = 0; t < nch; t++) {
        __syncthreads();
        #pragma unroll
        for (int i = 0; i < ALD; i++) {
            const int u = i * THREADS + tid;
            *(uint4*)(Asm + (u >> 3) * STR + (u & 7) * 8) = ra[i];
        }
        #pragma unroll
        for (int i = 0; i < BLD; i++) {
            const int u = i * THREADS + tid;
            *(uint4*)(Bsm + (u >> 3) * STR + (u & 7) * 8) = rb[i];
        }
        __syncthreads();
        if (t + 1 < nch) loadc(t + 1);

        #pragma unroll
        for (int ks = 0; ks < 4; ks++) {
            uint32_t af[MF][4], bfr[NF][2];
            #pragma unroll
            for (int mf = 0; mf < MF; mf++) {
                const __nv_bfloat16* ab = Asm + (wm + mf * 16 + (lane >> 2)) * STR
                                          + ks * 16 + (lane & 3) * 2;
                af[mf][0] = *(const uint32_t*)(ab);
                af[mf][1] = *(const uint32_t*)(ab + 8 * STR);
                af[mf][2] = *(const uint32_t*)(ab + 8);
                af[mf][3] = *(const uint32_t*)(ab + 8 * STR + 8);
            }
            #pragma unroll
            for (int nf = 0; nf < NF; nf++) {
                const __nv_bfloat16* bb = Bsm + (wn + nf * 8 + (lane >> 2)) * STR
                                          + ks * 16 + (lane & 3) * 2;
                bfr[nf][0] = *(const uint32_t*)(bb);
                bfr[nf][1] = *(const uint32_t*)(bb + 8);
            }
            #pragma unroll
            for (int mf = 0; mf < MF; mf++)
                #pragma unroll
                for (int nf = 0; nf < NF; nf++)
                    asm volatile(
                        "mma.sync.aligned.m16n8k16.row.col.f32.bf16.bf16.f32 "
                        "{%0,%1,%2,%3}, {%4,%5,%6,%7}, {%8,%9}, {%0,%1,%2,%3};"
                        : "+f"(acc[mf][nf][0]), "+f"(acc[mf][nf][1]),
                          "+f"(acc[mf][nf][2]), "+f"(acc[mf][nf][3])
                        : "r"(af[mf][0]), "r"(af[mf][1]), "r"(af[mf][2]), "r"(af[mf][3]),
                          "r"(bfr[nf][0]), "r"(bfr[nf][1]));
        }
    }

    #pragma unroll
    for (int mf = 0; mf < MF; mf++) {
        const int row = m0 + wm + mf * 16 + (lane >> 2);
        #pragma unroll
        for (int nf = 0; nf < NF; nf++) {
            const int col = n0 + wn + nf * 8 + (lane & 3) * 2;
            float2 v0 = { acc[mf][nf][0] * scale, acc[mf][nf][1] * scale };
            float2 v1 = { acc[mf][nf][2] * scale, acc[mf][nf][3] * scale };
            *(float2*)&C[(size_t)row * ldc + col] = v0;
            *(float2*)&C[(size_t)(row + 8) * ldc + col] = v1;
        }
    }
}

// ============================ conversion kernels ============================
__global__ void split_rows(const float* __restrict__ in, __nv_bfloat16* __restrict__ out,
                           size_t total) {
    const size_t i = (size_t)blockIdx.x * 256 + threadIdx.x;
    if (i >= total) return;
    const size_t m = i >> 10;
    const int k = (int)(i & 1023);
    __nv_bfloat16 h, l;
    split2(in[i], h, l);
    out[m * 2048 + k] = h;
    out[m * 2048 + 1024 + k] = l;
}

// rope + split: Y[4096][1024] f32 -> Qp[bh][2048][128] bf16 ([hi(64) | lo(64)])
__global__ void rope_split(const float* __restrict__ Y, __nv_bfloat16* __restrict__ Qp) {
    const int i = blockIdx.x * 256 + threadIdx.x;
    if (i >= Bn * Hn * Sn * 32) return;
    const int j = i & 31;
    const int s = (i >> 5) & (Sn - 1);
    const int bh = i >> 16;
    const int b = bh >> 4, h = bh & 15;
    const float* yr = Y + ((size_t)(b * Sn + s)) * En + h * 64;
    const float x1 = yr[j], x2 = yr[j + 32];
    const double invf = pow(10000.0, -(double)j / 32.0);
    const float ang = (float)((double)s * invf);
    const float sv = sinf(ang), cv = cosf(ang);
    const float r1 = x1 * cv - x2 * sv;
    const float r2 = x1 * sv + x2 * cv;
    __nv_bfloat16* o = Qp + ((size_t)bh * Sn + s) * 128;
    __nv_bfloat16 h1, l1, h2, l2;
    split2(r1, h1, l1);
    split2(r2, h2, l2);
    o[j] = h1; o[32 + j] = h2;
    o[64 + j] = l1; o[96 + j] = l2;
}

// transpose + split V: Y[4096][1024] f32 -> Vp[bh][64][4096] ([hi(2048) | lo(2048)])
__global__ void vsplit(const float* __restrict__ Yv, __nv_bfloat16* __restrict__ Vp) {
    __shared__ float t[64][65];
    const int bh = blockIdx.z, s0 = blockIdx.x * 64;
    const int b = bh >> 4, h = bh & 15;
    const int tid = threadIdx.x;
    #pragma unroll
    for (int i = 0; i < 16; i++) {
        const int u = i * 256 + tid;
        const int s = u >> 6, d = u & 63;
        t[s][d] = Yv[((size_t)(b * Sn + s0 + s)) * En + h * 64 + d];
    }
    __syncthreads();
    #pragma unroll
    for (int i = 0; i < 16; i++) {
        const int u = i * 256 + tid;
        const int d = u >> 6, s = u & 63;
        __nv_bfloat16 hh, ll;
        split2(t[s][d], hh, ll);
        __nv_bfloat16* o = Vp + ((size_t)bh * 64 + d) * 4096 + s0 + s;
        o[0] = hh;
        o[2048] = ll;
    }
}

// softmax in place (f32, causal) + split copy Wp[row][4096] = [hi | lo]
__global__ void softmax_split(float* __restrict__ Wm, __nv_bfloat16* __restrict__ Wp) {
    const int row = blockIdx.x;
    const int q = row & (Sn - 1);
    float* p = Wm + (size_t)row * Sn;
    __nv_bfloat16* o = Wp + (size_t)row * (2 * Sn);
    const int n = q + 1;
    const int tid = threadIdx.x;
    __shared__ float smax[8], ssum[8];

    float m = -FLT_MAX;
    for (int k = tid; k < n; k += 256) m = fmaxf(m, p[k]);
    #pragma unroll
    for (int off = 16; off; off >>= 1) m = fmaxf(m, __shfl_xor_sync(0xffffffffu, m, off));
    if ((tid & 31) == 0) smax[tid >> 5] = m;
    __syncthreads();
    if (tid == 0) {
        float mm = smax[0];
        #pragma unroll
        for (int i = 1; i < 8; i++) mm = fmaxf(mm, smax[i]);
        smax[0] = mm;
    }
    __syncthreads();
    m = smax[0];

    float sum = 0.f;
    for (int k = tid; k < n; k += 256) sum += expf(p[k] - m);
    #pragma unroll
    for (int off = 16; off; off >>= 1) sum += __shfl_xor_sync(0xffffffffu, sum, off);
    if ((tid & 31) == 0) ssum[tid >> 5] = sum;
    __syncthreads();
    if (tid == 0) {
        float s = 0.f;
        #pragma unroll
        for (int i = 0; i < 8; i++) s += ssum[i];
        ssum[0] = s;
    }
    __syncthreads();
    const float inv = 1.0f / ssum[0];

    const __nv_bfloat16 z = __float2bfloat16(0.f);
    for (int k = tid; k < n; k += 256) {
        const float e = expf(p[k] - m) * inv;
        p[k] = e;
        __nv_bfloat16 h, l;
        split2(e, h, l);
        o[k] = h;
        o[Sn + k] = l;
    }
    for (int k = n + tid; k < Sn; k += 256) {
        p[k] = 0.f;
        o[k] = z;
        o[Sn + k] = z;
    }
}

// ctx1*ctx2, pack [bh][s][d] -> [m=b*S+s][2048] split rows ([hi(1024)|lo(1024)])
__global__ void mulpack_split(const float* __restrict__ C1, const float* __restrict__ C2,
                              __nv_bfloat16* __restrict__ Pp) {
    const size_t i = (size_t)blockIdx.x * 256 + threadIdx.x;
    if (i >= QSZ) return;
    const float v = C1[i] * C2[i];
    const int d = (int)(i & 63);
    const size_t r = i >> 6;
    const int s = (int)(r & (Sn - 1));
    const int bh = (int)(r >> 11);
    const int b = bh >> 4, h = bh & 15;
    const size_t m = (size_t)(b * Sn + s);
    __nv_bfloat16 hh, ll;
    split2(v, hh, ll);
    Pp[m * 2048 + h * 64 + d] = hh;
    Pp[m * 2048 + 1024 + h * 64 + d] = ll;
}

// ============================ launch ============================
extern "C" void kernel_launch(void* const* d_in, const int* in_sizes, int n_in,
                              void* d_out, int out_size) {
    const float* query = (const float*)d_in[0];
    const float* key   = (const float*)d_in[1];
    const float* value = (const float*)d_in[2];
    // d_in[3] = mask (causal tril, hardcoded)
    const float* Wf[7] = {
        (const float*)d_in[4],  (const float*)d_in[5], (const float*)d_in[6],
        (const float*)d_in[7],  (const float*)d_in[8], (const float*)d_in[9],
        (const float*)d_in[10]  // WQ1 WK1 WV1 WQ2 WK2 WV2 WO
    };

    float* out = (float*)d_out;
    float* w1  = out + (size_t)M_ROWS * En;
    float* w2  = w1 + WSZ;

    unsigned char* sc = nullptr;
    cudaGetSymbolAddress((void**)&sc, g_scratch);

    __nv_bfloat16* XQ = (__nv_bfloat16*)(sc + 0 * MBb);
    __nv_bfloat16* XK = (__nv_bfloat16*)(sc + 16 * MBb);
    __nv_bfloat16* XV = (__nv_bfloat16*)(sc + 32 * MBb);
    __nv_bfloat16* WC[7];
    for (int i = 0; i < 7; i++) WC[i] = (__nv_bfloat16*)(sc + (48 + 4 * i) * MBb);
    float* Y[6];
    for (int i = 0; i < 6; i++) Y[i] = (float*)(sc + (76 + 16 * i) * MBb);
    __nv_bfloat16* QS[4];
    for (int i = 0; i < 4; i++) QS[i] = (__nv_bfloat16*)(sc + (172 + 16 * i) * MBb);
    __nv_bfloat16* VT[2];
    for (int i = 0; i < 2; i++) VT[i] = (__nv_bfloat16*)(sc + (236 + 16 * i) * MBb);
    __nv_bfloat16* WP = (__nv_bfloat16*)(sc + 268 * MBb);
    float* CC[2];
    for (int i = 0; i < 2; i++) CC[i] = (float*)(sc + (780 + 16 * i) * MBb);
    __nv_bfloat16* PP = (__nv_bfloat16*)(sc + 812 * MBb);

    // 1) split fp32 -> bf16 [hi|lo]
    const size_t totX = (size_t)M_ROWS * En;
    split_rows<<<(unsigned)((totX + 255) / 256), 256>>>(query, XQ, totX);
    split_rows<<<(unsigned)((totX + 255) / 256), 256>>>(key,   XK, totX);
    split_rows<<<(unsigned)((totX + 255) / 256), 256>>>(value, XV, totX);
    const size_t totW = (size_t)En * En;
    for (int i = 0; i < 7; i++)
        split_rows<<<(unsigned)((totW + 255) / 256), 256>>>(Wf[i], WC[i], totW);

    // 2) projections: [4096 x 1024] f32 outputs
    const dim3 gproj(En / 128, M_ROWS / 128, 1);   // (8, 32)
    gemm_mma<128,2,4><<<gproj, 256>>>(XQ, WC[0], Y[0], 0,0,0, 2048, 2048, En, En, 1.f, 0);
    gemm_mma<128,2,4><<<gproj, 256>>>(XK, WC[1], Y[1], 0,0,0, 2048, 2048, En, En, 1.f, 0);
    gemm_mma<128,2,4><<<gproj, 256>>>(XV, WC[2], Y[2], 0,0,0, 2048, 2048, En, En, 1.f, 0);
    gemm_mma<128,2,4><<<gproj, 256>>>(XQ, WC[3], Y[3], 0,0,0, 2048, 2048, En, En, 1.f, 0);
    gemm_mma<128,2,4><<<gproj, 256>>>(XK, WC[4], Y[4], 0,0,0, 2048, 2048, En, En, 1.f, 0);
    gemm_mma<128,2,4><<<gproj, 256>>>(XV, WC[5], Y[5], 0,0,0, 2048, 2048, En, En, 1.f, 0);

    // 3) rope + split Q/K; transpose-split V
    const int re = Bn * Hn * Sn * 32;
    rope_split<<<re / 256, 256>>>(Y[0], QS[0]);
    rope_split<<<re / 256, 256>>>(Y[1], QS[1]);
    rope_split<<<re / 256, 256>>>(Y[3], QS[2]);
    rope_split<<<re / 256, 256>>>(Y[4], QS[3]);
    vsplit<<<dim3(Sn / 64, 1, Bn * Hn), 256>>>(Y[2], VT[0]);
    vsplit<<<dim3(Sn / 64, 1, Bn * Hn), 256>>>(Y[5], VT[1]);

    // 4) head 1: scores -> softmax(+split) -> ctx
    gemm_mma<128,2,4><<<dim3(Sn / 128, Sn / 128, Bn * Hn), 256>>>(
        QS[0], QS[1], w1, (long long)Sn * 128, (long long)Sn * 128, (long long)Sn * Sn,
        128, 128, Sn, Dn, 0.125f, 1);
    softmax_split<<<Bn * Hn * Sn, 256>>>(w1, WP);
    gemm_mma<64,4,2><<<dim3(1, Sn / 128, Bn * Hn), 256>>>(
        WP, VT[0], CC[0], (long long)Sn * 4096, (long long)64 * 4096, (long long)Sn * 64,
        4096, 4096, 64, Sn, 1.f, 2);

    // 5) head 2
    gemm_mma<128,2,4><<<dim3(Sn / 128, Sn / 128, Bn * Hn), 256>>>(
        QS[2], QS[3], w2, (long long)Sn * 128, (long long)Sn * 128, (long long)Sn * Sn,
        128, 128, Sn, Dn, 0.125f, 1);
    softmax_split<<<Bn * Hn * Sn, 256>>>(w2, WP);
    gemm_mma<64,4,2><<<dim3(1, Sn / 128, Bn * Hn), 256>>>(
        WP, VT[1], CC[1], (long long)Sn * 4096, (long long)64 * 4096, (long long)Sn * 64,
        4096, 4096, 64, Sn, 1.f, 2);

    // 6) multiply, pack+split, output projection
    mulpack_split<<<(unsigned)((QSZ + 255) / 256), 256>>>(CC[0], CC[1], PP);
    gemm_mma<128,2,4><<<gproj, 256>>>(PP, WC[6], out, 0,0,0, 2048, 2048, En, En, 1.f, 0);
}

// round 5
// speedup vs baseline: 1.6382x; 1.1176x over previous
#include <cuda_runtime.h>
#include <cuda_fp16.h>
#include <cstdint>
#include <float.h>
#include <math.h>

#define Bn 2
#define Sn 2048
#define Hn 16
#define Dn 64
#define En 1024
#define M_ROWS (Bn*Sn)
#define QSZ ((size_t)Bn*Hn*Sn*Dn)
#define WSZ ((size_t)Bn*Hn*Sn*Sn)
#define MBb (1024ull*1024ull)

// scratch (MB offsets): Y[6]=16i, QK[4]=96+16i, VT[2]=160+16i, CC[2]=192+16i, PK=224
__device__ __align__(1024) unsigned char g_scratch[240 * 1024 * 1024];

__device__ __forceinline__ uint32_t packh2(float a, float b) {
    __half2 h = __halves2half2(__float2half_rn(a), __float2half_rn(b));
    return *(uint32_t*)&h;
}

// ============================================================================
// f32-in GEMM on fp16 mma.sync with in-kernel 2-term split, 3 combos per chunk.
// C[m,n] = scale * sum_k A[m,k] * B[n,k]
// BM=128, chunk K=64. mode: 0 none, 1 causal tile-skip, 2 causal kmax.
// dynamic smem: Ah/Al [BM*STR] + Bh/Bl [BN*STR] halves.
// ============================================================================
template<int BN, int WR, int WCn>
__global__ void __launch_bounds__(256, 2) gemm_f32h(
    const float* __restrict__ A, const float* __restrict__ B, float* __restrict__ C,
    long long sAz, long long sBz, long long sCz,
    int lda, int ldb, int ldc, int Kblk, float scale, int mode)
{
    constexpr int BM = 128, STR = 72;
    constexpr int THREADS = 256;
    constexpr int WM = BM / WR, WN = BN / WCn;
    constexpr int MF = WM / 16, NF = WN / 8;
    constexpr int ALD = BM * 64 / (4 * THREADS);   // 8
    constexpr int BLD = BN * 64 / (4 * THREADS);   // 8 or 4

    const int m0 = blockIdx.y * BM;
    const int n0 = blockIdx.x * BN;
    if (mode == 1 && n0 > m0 + BM - 1) return;
    const int kmax = (mode == 2) ? min(Kblk, m0 + BM) : Kblk;
    const int nk = kmax >> 6;

    A += (size_t)blockIdx.z * sAz;
    B += (size_t)blockIdx.z * sBz;
    C += (size_t)blockIdx.z * sCz;

    extern __shared__ __align__(16) unsigned char dsm[];
    half* Ah = (half*)dsm;
    half* Al = Ah + BM * STR;
    half* Bh = Al + BM * STR;
    half* Bl = Bh + BN * STR;

    const int tid = threadIdx.x;
    const int lane = tid & 31;
    const int w = tid >> 5;
    const int wm = (w / WCn) * WM;
    const int wn = (w % WCn) * WN;

    float acc[MF][NF][4] = {};

    for (int kc = 0; kc < nk; kc++) {
        __syncthreads();
        #pragma unroll
        for (int i = 0; i < ALD; i++) {
            const int u = i * THREADS + tid;
            const int row = u >> 4, c4 = (u & 15) * 4;
            const float4 v = *(const float4*)(A + (size_t)(m0 + row) * lda + kc * 64 + c4);
            const float hx = __half2float(__float2half_rn(v.x));
            const float hy = __half2float(__float2half_rn(v.y));
            const float hz = __half2float(__float2half_rn(v.z));
            const float hw = __half2float(__float2half_rn(v.w));
            uint2 Hi = { packh2(v.x, v.y), packh2(v.z, v.w) };
            uint2 Lo = { packh2(v.x - hx, v.y - hy), packh2(v.z - hz, v.w - hw) };
            *(uint2*)&Ah[row * STR + c4] = Hi;
            *(uint2*)&Al[row * STR + c4] = Lo;
        }
        #pragma unroll
        for (int i = 0; i < BLD; i++) {
            const int u = i * THREADS + tid;
            const int row = u >> 4, c4 = (u & 15) * 4;
            const float4 v = *(const float4*)(B + (size_t)(n0 + row) * ldb + kc * 64 + c4);
            const float hx = __half2float(__float2half_rn(v.x));
            const float hy = __half2float(__float2half_rn(v.y));
            const float hz = __half2float(__float2half_rn(v.z));
            const float hw = __half2float(__float2half_rn(v.w));
            uint2 Hi = { packh2(v.x, v.y), packh2(v.z, v.w) };
            uint2 Lo = { packh2(v.x - hx, v.y - hy), packh2(v.z - hz, v.w - hw) };
            *(uint2*)&Bh[row * STR + c4] = Hi;
            *(uint2*)&Bl[row * STR + c4] = Lo;
        }
        __syncthreads();

        #pragma unroll
        for (int combo = 0; combo < 3; combo++) {
            const half* As = (combo == 2) ? Al : Ah;
            const half* Bs = (combo == 1) ? Bl : Bh;
            #pragma unroll
            for (int ks = 0; ks < 4; ks++) {
                uint32_t af[MF][4], bfr[NF][2];
                #pragma unroll
                for (int mf = 0; mf < MF; mf++) {
                    const half* ab = As + (wm + mf * 16 + (lane >> 2)) * STR
                                     + ks * 16 + (lane & 3) * 2;
                    af[mf][0] = *(const uint32_t*)(ab);
                    af[mf][1] = *(const uint32_t*)(ab + 8 * STR);
                    af[mf][2] = *(const uint32_t*)(ab + 8);
                    af[mf][3] = *(const uint32_t*)(ab + 8 * STR + 8);
                }
                #pragma unroll
                for (int nf = 0; nf < NF; nf++) {
                    const half* bb = Bs + (wn + nf * 8 + (lane >> 2)) * STR
                                     + ks * 16 + (lane & 3) * 2;
                    bfr[nf][0] = *(const uint32_t*)(bb);
                    bfr[nf][1] = *(const uint32_t*)(bb + 8);
                }
                #pragma unroll
                for (int mf = 0; mf < MF; mf++)
                    #pragma unroll
                    for (int nf = 0; nf < NF; nf++)
                        asm volatile(
                            "mma.sync.aligned.m16n8k16.row.col.f32.f16.f16.f32 "
                            "{%0,%1,%2,%3}, {%4,%5,%6,%7}, {%8,%9}, {%0,%1,%2,%3};"
                            : "+f"(acc[mf][nf][0]), "+f"(acc[mf][nf][1]),
                              "+f"(acc[mf][nf][2]), "+f"(acc[mf][nf][3])
                            : "r"(af[mf][0]), "r"(af[mf][1]), "r"(af[mf][2]), "r"(af[mf][3]),
                              "r"(bfr[nf][0]), "r"(bfr[nf][1]));
            }
        }
    }

    #pragma unroll
    for (int mf = 0; mf < MF; mf++) {
        const int row = m0 + wm + mf * 16 + (lane >> 2);
        #pragma unroll
        for (int nf = 0; nf < NF; nf++) {
            const int col = n0 + wn + nf * 8 + (lane & 3) * 2;
            float2 v0 = { acc[mf][nf][0] * scale, acc[mf][nf][1] * scale };
            float2 v1 = { acc[mf][nf][2] * scale, acc[mf][nf][3] * scale };
            *(float2*)&C[(size_t)row * ldc + col] = v0;
            *(float2*)&C[(size_t)(row + 8) * ldc + col] = v1;
        }
    }
}

// ============================ aux kernels ============================
// rope: Y[m=b*S+s][h*64+d] -> Qr[bh][s][d], f32
__global__ void rope_f32(const float* __restrict__ Y, float* __restrict__ Qr) {
    const int i = blockIdx.x * 256 + threadIdx.x;
    if (i >= Bn * Hn * Sn * 32) return;
    const int j = i & 31;
    const int s = (i >> 5) & (Sn - 1);
    const int bh = i >> 16;
    const int b = bh >> 4, h = bh & 15;
    const float* yr = Y + ((size_t)(b * Sn + s)) * En + h * 64;
    const float x1 = yr[j], x2 = yr[j + 32];
    const double invf = pow(10000.0, -(double)j / 32.0);
    const float ang = (float)((double)s * invf);
    const float sv = sinf(ang), cv = cosf(ang);
    float* o = Qr + ((size_t)bh * Sn + s) * 64;
    o[j]      = x1 * cv - x2 * sv;
    o[j + 32] = x1 * sv + x2 * cv;
}

// V transpose: Y[m][h*64+d] -> VT[bh][d][s], f32
__global__ void vtrans(const float* __restrict__ Yv, float* __restrict__ VT) {
    __shared__ float t[64][65];
    const int bh = blockIdx.z, s0 = blockIdx.x * 64;
    const int b = bh >> 4, h = bh & 15;
    const int tid = threadIdx.x;
    #pragma unroll
    for (int i = 0; i < 16; i++) {
        const int u = i * 256 + tid;
        const int s = u >> 6, d = u & 63;
        t[s][d] = Yv[((size_t)(b * Sn + s0 + s)) * En + h * 64 + d];
    }
    __syncthreads();
    #pragma unroll
    for (int i = 0; i < 16; i++) {
        const int u = i * 256 + tid;
        const int d = u >> 6, s = u & 63;
        VT[((size_t)bh * 64 + d) * Sn + s0 + s] = t[s][d];
    }
}

// register-cached causal softmax in place: 1 read + 1 write per row
__global__ void softmax_reg(float* __restrict__ Wm) {
    const int row = blockIdx.x;
    const int q = row & (Sn - 1);
    float* p = Wm + (size_t)row * Sn;
    const int tid = threadIdx.x;
    const int c0 = tid * 4, c1 = 1024 + tid * 4;
    __shared__ float red[8];

    float4 a = *(float4*)(p + c0);
    float4 b = *(float4*)(p + c1);
    float v[8] = { a.x, a.y, a.z, a.w, b.x, b.y, b.z, b.w };

    float m = -1e30f;
    #pragma unroll
    for (int j = 0; j < 8; j++) {
        const int col = (j < 4) ? (c0 + j) : (c1 + j - 4);
        if (col <= q) m = fmaxf(m, v[j]);
    }
    #pragma unroll
    for (int o = 16; o; o >>= 1) m = fmaxf(m, __shfl_xor_sync(0xffffffffu, m, o));
    if ((tid & 31) == 0) red[tid >> 5] = m;
    __syncthreads();
    if (tid < 32) {
        float mm = (tid < 8) ? red[tid] : -1e30f;
        #pragma unroll
        for (int o = 4; o; o >>= 1) mm = fmaxf(mm, __shfl_xor_sync(0xffffffffu, mm, o));
        if (tid == 0) red[0] = mm;
    }
    __syncthreads();
    m = red[0];
    __syncthreads();

    float sum = 0.f;
    #pragma unroll
    for (int j = 0; j < 8; j++) {
        const int col = (j < 4) ? (c0 + j) : (c1 + j - 4);
        v[j] = (col <= q) ? expf(v[j] - m) : 0.f;
        sum += v[j];
    }
    #pragma unroll
    for (int o = 16; o; o >>= 1) sum += __shfl_xor_sync(0xffffffffu, sum, o);
    if ((tid & 31) == 0) red[tid >> 5] = sum;
    __syncthreads();
    if (tid < 32) {
        float s = (tid < 8) ? red[tid] : 0.f;
        #pragma unroll
        for (int o = 4; o; o >>= 1) s += __shfl_xor_sync(0xffffffffu, s, o);
        if (tid == 0) red[0] = s;
    }
    __syncthreads();
    const float inv = 1.0f / red[0];

    a.x = v[0] * inv; a.y = v[1] * inv; a.z = v[2] * inv; a.w = v[3] * inv;
    b.x = v[4] * inv; b.y = v[5] * inv; b.z = v[6] * inv; b.w = v[7] * inv;
    *(float4*)(p + c0) = a;
    *(float4*)(p + c1) = b;
}

// ctx1*ctx2, pack [bh][s][d] -> PK[m=b*S+s][h*64+d], f32
__global__ void mulpack(const float* __restrict__ C1, const float* __restrict__ C2,
                        float* __restrict__ PK) {
    const size_t i = (size_t)blockIdx.x * 256 + threadIdx.x;
    if (i >= QSZ) return;
    const float v = C1[i] * C2[i];
    const int d = (int)(i & 63);
    const size_t r = i >> 6;
    const int s = (int)(r & (Sn - 1));
    const int bh = (int)(r >> 11);
    const int b = bh >> 4, h = bh & 15;
    PK[((size_t)(b * Sn + s)) * En + h * 64 + d] = v;
}

// ============================ launch ============================
extern "C" void kernel_launch(void* const* d_in, const int* in_sizes, int n_in,
                              void* d_out, int out_size) {
    const float* query = (const float*)d_in[0];
    const float* key   = (const float*)d_in[1];
    const float* value = (const float*)d_in[2];
    // d_in[3] = mask (causal tril, hardcoded)
    const float* Wf[7] = {
        (const float*)d_in[4],  (const float*)d_in[5], (const float*)d_in[6],
        (const float*)d_in[7],  (const float*)d_in[8], (const float*)d_in[9],
        (const float*)d_in[10]  // WQ1 WK1 WV1 WQ2 WK2 WV2 WO
    };

    float* out = (float*)d_out;
    float* w1  = out + (size_t)M_ROWS * En;
    float* w2  = w1 + WSZ;

    unsigned char* sc = nullptr;
    cudaGetSymbolAddress((void**)&sc, g_scratch);

    float* Y[6];
    for (int i = 0; i < 6; i++) Y[i] = (float*)(sc + (size_t)(16 * i) * MBb);
    float* QK[4];
    for (int i = 0; i < 4; i++) QK[i] = (float*)(sc + (size_t)(96 + 16 * i) * MBb);
    float* VT[2];
    for (int i = 0; i < 2; i++) VT[i] = (float*)(sc + (size_t)(160 + 16 * i) * MBb);
    float* CC[2];
    for (int i = 0; i < 2; i++) CC[i] = (float*)(sc + (size_t)(192 + 16 * i) * MBb);
    float* PK = (float*)(sc + (size_t)224 * MBb);

    const int SMEM_BIG = (128 + 128) * 72 * 2 * 2;   // 73728
    const int SMEM_CTX = (128 + 64) * 72 * 2 * 2;    // 55296
    cudaFuncSetAttribute((const void*)&gemm_f32h<128, 2, 4>,
                         cudaFuncAttributeMaxDynamicSharedMemorySize, SMEM_BIG);
    cudaFuncSetAttribute((const void*)&gemm_f32h<64, 4, 2>,
                         cudaFuncAttributeMaxDynamicSharedMemorySize, SMEM_CTX);

    // 1) projections: f32 inputs straight in
    const dim3 gproj(En / 128, M_ROWS / 128, 1);   // (8, 32)
    gemm_f32h<128,2,4><<<gproj, 256, SMEM_BIG>>>(query, Wf[0], Y[0], 0,0,0, En, En, En, En, 1.f, 0);
    gemm_f32h<128,2,4><<<gproj, 256, SMEM_BIG>>>(key,   Wf[1], Y[1], 0,0,0, En, En, En, En, 1.f, 0);
    gemm_f32h<128,2,4><<<gproj, 256, SMEM_BIG>>>(value, Wf[2], Y[2], 0,0,0, En, En, En, En, 1.f, 0);
    gemm_f32h<128,2,4><<<gproj, 256, SMEM_BIG>>>(query, Wf[3], Y[3], 0,0,0, En, En, En, En, 1.f, 0);
    gemm_f32h<128,2,4><<<gproj, 256, SMEM_BIG>>>(key,   Wf[4], Y[4], 0,0,0, En, En, En, En, 1.f, 0);
    gemm_f32h<128,2,4><<<gproj, 256, SMEM_BIG>>>(value, Wf[5], Y[5], 0,0,0, En, En, En, En, 1.f, 0);

    // 2) rope Q/K, transpose V
    const int re = Bn * Hn * Sn * 32;
    rope_f32<<<re / 256, 256>>>(Y[0], QK[0]);
    rope_f32<<<re / 256, 256>>>(Y[1], QK[1]);
    rope_f32<<<re / 256, 256>>>(Y[3], QK[2]);
    rope_f32<<<re / 256, 256>>>(Y[4], QK[3]);
    vtrans<<<dim3(Sn / 64, 1, Bn * Hn), 256>>>(Y[2], VT[0]);
    vtrans<<<dim3(Sn / 64, 1, Bn * Hn), 256>>>(Y[5], VT[1]);

    // 3) scores (causal tile-skip), softmax in place, ctx (causal kmax)
    const dim3 gsc(Sn / 128, Sn / 128, Bn * Hn);
    gemm_f32h<128,2,4><<<gsc, 256, SMEM_BIG>>>(
        QK[0], QK[1], w1, (long long)Sn * 64, (long long)Sn * 64, (long long)Sn * Sn,
        64, 64, Sn, 64, 0.125f, 1);
    softmax_reg<<<Bn * Hn * Sn, 256>>>(w1);
    gemm_f32h<64,4,2><<<dim3(1, Sn / 128, Bn * Hn), 256, SMEM_CTX>>>(
        w1, VT[0], CC[0], (long long)Sn * Sn, (long long)64 * Sn, (long long)Sn * 64,
        Sn, Sn, 64, Sn, 1.f, 2);

    gemm_f32h<128,2,4><<<gsc, 256, SMEM_BIG>>>(
        QK[2], QK[3], w2, (long long)Sn * 64, (long long)Sn * 64, (long long)Sn * Sn,
        64, 64, Sn, 64, 0.125f, 1);
    softmax_reg<<<Bn * Hn * Sn, 256>>>(w2);
    gemm_f32h<64,4,2><<<dim3(1, Sn / 128, Bn * Hn), 256, SMEM_CTX>>>(
        w2, VT[1], CC[1], (long long)Sn * Sn, (long long)64 * Sn, (long long)Sn * 64,
        Sn, Sn, 64, Sn, 1.f, 2);

    // 4) multiply+pack, output projection
    mulpack<<<(unsigned)((QSZ + 255) / 256), 256>>>(CC[0], CC[1], PK);
    gemm_f32h<128,2,4><<<gproj, 256, SMEM_BIG>>>(PK, Wf[6], out, 0,0,0, En, En, En, En, 1.f, 0);
}

// round 6
// speedup vs baseline: 1.7137x; 1.0461x over previous
#include <cuda_runtime.h>
#include <cuda_fp16.h>
#include <cstdint>
#include <float.h>
#include <math.h>

#define Bn 2
#define Sn 2048
#define Hn 16
#define Dn 64
#define En 1024
#define M_ROWS (Bn*Sn)
#define QSZ ((size_t)Bn*Hn*Sn*Dn)
#define WSZ ((size_t)Bn*Hn*Sn*Sn)
#define MBb (1024ull*1024ull)

// scratch (MB offsets): Y[6]=16i, QK[4]=96+16i, VT[2]=160+16i, CC[2]=192+16i, PK=224
__device__ __align__(1024) unsigned char g_scratch[240 * 1024 * 1024];

__device__ __forceinline__ uint32_t packh2(float a, float b) {
    __half2 h = __halves2half2(__float2half_rn(a), __float2half_rn(b));
    return *(uint32_t*)&h;
}

// ============================================================================
// f32-in GEMM on fp16 mma.sync, in-kernel 2-term split, 3 combos per chunk,
// register-prefetch of next chunk overlapping the MMA phase.
// C[m,n] = scale * sum_k A[m,k] * B[n,k]
// BM=128, chunk K=64. mode: 0 none, 1 causal tile-skip, 2 causal kmax.
// ============================================================================
template<int BN, int WR, int WCn>
__global__ void __launch_bounds__(256) gemm_f32h(
    const float* __restrict__ A, const float* __restrict__ B, float* __restrict__ C,
    long long sAz, long long sBz, long long sCz,
    int lda, int ldb, int ldc, int Kblk, float scale, int mode)
{
    constexpr int BM = 128, STR = 72;
    constexpr int THREADS = 256;
    constexpr int WM = BM / WR, WN = BN / WCn;
    constexpr int MF = WM / 16, NF = WN / 8;
    constexpr int ALD = BM * 64 / (4 * THREADS);   // 8
    constexpr int BLD = BN * 64 / (4 * THREADS);   // 8 (BN=128) or 4 (BN=64)

    const int m0 = blockIdx.y * BM;
    const int n0 = blockIdx.x * BN;
    if (mode == 1 && n0 > m0 + BM - 1) return;
    const int kmax = (mode == 2) ? min(Kblk, m0 + BM) : Kblk;
    const int nk = kmax >> 6;

    A += (size_t)blockIdx.z * sAz;
    B += (size_t)blockIdx.z * sBz;
    C += (size_t)blockIdx.z * sCz;

    extern __shared__ __align__(16) unsigned char dsm[];
    half* Ah = (half*)dsm;
    half* Al = Ah + BM * STR;
    half* Bh = Al + BM * STR;
    half* Bl = Bh + BN * STR;

    const int tid = threadIdx.x;
    const int lane = tid & 31;
    const int w = tid >> 5;
    const int wm = (w / WCn) * WM;
    const int wn = (w % WCn) * WN;

    float acc[MF][NF][4] = {};
    float4 pa[ALD], pb[BLD];

    auto gload = [&](int kc) {
        #pragma unroll
        for (int i = 0; i < ALD; i++) {
            const int u = i * THREADS + tid;
            pa[i] = *(const float4*)(A + (size_t)(m0 + (u >> 4)) * lda + kc * 64 + (u & 15) * 4);
        }
        #pragma unroll
        for (int i = 0; i < BLD; i++) {
            const int u = i * THREADS + tid;
            pb[i] = *(const float4*)(B + (size_t)(n0 + (u >> 4)) * ldb + kc * 64 + (u & 15) * 4);
        }
    };

    gload(0);
    for (int kc = 0; kc < nk; kc++) {
        __syncthreads();
        #pragma unroll
        for (int i = 0; i < ALD; i++) {
            const int u = i * THREADS + tid;
            const int row = u >> 4, c4 = (u & 15) * 4;
            const float4 v = pa[i];
            const float hx = __half2float(__float2half_rn(v.x));
            const float hy = __half2float(__float2half_rn(v.y));
            const float hz = __half2float(__float2half_rn(v.z));
            const float hw = __half2float(__float2half_rn(v.w));
            uint2 Hi = { packh2(v.x, v.y), packh2(v.z, v.w) };
            uint2 Lo = { packh2(v.x - hx, v.y - hy), packh2(v.z - hz, v.w - hw) };
            *(uint2*)&Ah[row * STR + c4] = Hi;
            *(uint2*)&Al[row * STR + c4] = Lo;
        }
        #pragma unroll
        for (int i = 0; i < BLD; i++) {
            const int u = i * THREADS + tid;
            const int row = u >> 4, c4 = (u & 15) * 4;
            const float4 v = pb[i];
            const float hx = __half2float(__float2half_rn(v.x));
            const float hy = __half2float(__float2half_rn(v.y));
            const float hz = __half2float(__float2half_rn(v.z));
            const float hw = __half2float(__float2half_rn(v.w));
            uint2 Hi = { packh2(v.x, v.y), packh2(v.z, v.w) };
            uint2 Lo = { packh2(v.x - hx, v.y - hy), packh2(v.z - hz, v.w - hw) };
            *(uint2*)&Bh[row * STR + c4] = Hi;
            *(uint2*)&Bl[row * STR + c4] = Lo;
        }
        __syncthreads();
        if (kc + 1 < nk) gload(kc + 1);

        #pragma unroll
        for (int combo = 0; combo < 3; combo++) {
            const half* As = (combo == 2) ? Al : Ah;
            const half* Bs = (combo == 1) ? Bl : Bh;
            #pragma unroll
            for (int ks = 0; ks < 4; ks++) {
                uint32_t af[MF][4], bfr[NF][2];
                #pragma unroll
                for (int mf = 0; mf < MF; mf++) {
                    const half* ab = As + (wm + mf * 16 + (lane >> 2)) * STR
                                     + ks * 16 + (lane & 3) * 2;
                    af[mf][0] = *(const uint32_t*)(ab);
                    af[mf][1] = *(const uint32_t*)(ab + 8 * STR);
                    af[mf][2] = *(const uint32_t*)(ab + 8);
                    af[mf][3] = *(const uint32_t*)(ab + 8 * STR + 8);
                }
                #pragma unroll
                for (int nf = 0; nf < NF; nf++) {
                    const half* bb = Bs + (wn + nf * 8 + (lane >> 2)) * STR
                                     + ks * 16 + (lane & 3) * 2;
                    bfr[nf][0] = *(const uint32_t*)(bb);
                    bfr[nf][1] = *(const uint32_t*)(bb + 8);
                }
                #pragma unroll
                for (int mf = 0; mf < MF; mf++)
                    #pragma unroll
                    for (int nf = 0; nf < NF; nf++)
                        asm volatile(
                            "mma.sync.aligned.m16n8k16.row.col.f32.f16.f16.f32 "
                            "{%0,%1,%2,%3}, {%4,%5,%6,%7}, {%8,%9}, {%0,%1,%2,%3};"
                            : "+f"(acc[mf][nf][0]), "+f"(acc[mf][nf][1]),
                              "+f"(acc[mf][nf][2]), "+f"(acc[mf][nf][3])
                            : "r"(af[mf][0]), "r"(af[mf][1]), "r"(af[mf][2]), "r"(af[mf][3]),
                              "r"(bfr[nf][0]), "r"(bfr[nf][1]));
            }
        }
    }

    #pragma unroll
    for (int mf = 0; mf < MF; mf++) {
        const int row = m0 + wm + mf * 16 + (lane >> 2);
        #pragma unroll
        for (int nf = 0; nf < NF; nf++) {
            const int col = n0 + wn + nf * 8 + (lane & 3) * 2;
            float2 v0 = { acc[mf][nf][0] * scale, acc[mf][nf][1] * scale };
            float2 v1 = { acc[mf][nf][2] * scale, acc[mf][nf][3] * scale };
            *(float2*)&C[(size_t)row * ldc + col] = v0;
            *(float2*)&C[(size_t)(row + 8) * ldc + col] = v1;
        }
    }
}

// ============================ aux kernels ============================
__global__ void rope_f32(const float* __restrict__ Y, float* __restrict__ Qr) {
    const int i = blockIdx.x * 256 + threadIdx.x;
    if (i >= Bn * Hn * Sn * 32) return;
    const int j = i & 31;
    const int s = (i >> 5) & (Sn - 1);
    const int bh = i >> 16;
    const int b = bh >> 4, h = bh & 15;
    const float* yr = Y + ((size_t)(b * Sn + s)) * En + h * 64;
    const float x1 = yr[j], x2 = yr[j + 32];
    const double invf = pow(10000.0, -(double)j / 32.0);
    const float ang = (float)((double)s * invf);
    const float sv = sinf(ang), cv = cosf(ang);
    float* o = Qr + ((size_t)bh * Sn + s) * 64;
    o[j]      = x1 * cv - x2 * sv;
    o[j + 32] = x1 * sv + x2 * cv;
}

__global__ void vtrans(const float* __restrict__ Yv, float* __restrict__ VT) {
    __shared__ float t[64][65];
    const int bh = blockIdx.z, s0 = blockIdx.x * 64;
    const int b = bh >> 4, h = bh & 15;
    const int tid = threadIdx.x;
    #pragma unroll
    for (int i = 0; i < 16; i++) {
        const int u = i * 256 + tid;
        const int s = u >> 6, d = u & 63;
        t[s][d] = Yv[((size_t)(b * Sn + s0 + s)) * En + h * 64 + d];
    }
    __syncthreads();
    #pragma unroll
    for (int i = 0; i < 16; i++) {
        const int u = i * 256 + tid;
        const int d = u >> 6, s = u & 63;
        VT[((size_t)bh * 64 + d) * Sn + s0 + s] = t[s][d];
    }
}

// register-cached causal softmax in place: 1 read + 1 write per row
__global__ void softmax_reg(float* __restrict__ Wm) {
    const int row = blockIdx.x;
    const int q = row & (Sn - 1);
    float* p = Wm + (size_t)row * Sn;
    const int tid = threadIdx.x;
    const int c0 = tid * 4, c1 = 1024 + tid * 4;
    __shared__ float red[8];

    float4 a = *(float4*)(p + c0);
    float4 b = *(float4*)(p + c1);
    float v[8] = { a.x, a.y, a.z, a.w, b.x, b.y, b.z, b.w };

    float m = -1e30f;
    #pragma unroll
    for (int j = 0; j < 8; j++) {
        const int col = (j < 4) ? (c0 + j) : (c1 + j - 4);
        if (col <= q) m = fmaxf(m, v[j]);
    }
    #pragma unroll
    for (int o = 16; o; o >>= 1) m = fmaxf(m, __shfl_xor_sync(0xffffffffu, m, o));
    if ((tid & 31) == 0) red[tid >> 5] = m;
    __syncthreads();
    if (tid < 32) {
        float mm = (tid < 8) ? red[tid] : -1e30f;
        #pragma unroll
        for (int o = 4; o; o >>= 1) mm = fmaxf(mm, __shfl_xor_sync(0xffffffffu, mm, o));
        if (tid == 0) red[0] = mm;
    }
    __syncthreads();
    m = red[0];
    __syncthreads();

    float sum = 0.f;
    #pragma unroll
    for (int j = 0; j < 8; j++) {
        const int col = (j < 4) ? (c0 + j) : (c1 + j - 4);
        v[j] = (col <= q) ? expf(v[j] - m) : 0.f;
        sum += v[j];
    }
    #pragma unroll
    for (int o = 16; o; o >>= 1) sum += __shfl_xor_sync(0xffffffffu, sum, o);
    if ((tid & 31) == 0) red[tid >> 5] = sum;
    __syncthreads();
    if (tid < 32) {
        float s = (tid < 8) ? red[tid] : 0.f;
        #pragma unroll
        for (int o = 4; o; o >>= 1) s += __shfl_xor_sync(0xffffffffu, s, o);
        if (tid == 0) red[0] = s;
    }
    __syncthreads();
    const float inv = 1.0f / red[0];

    a.x = v[0] * inv; a.y = v[1] * inv; a.z = v[2] * inv; a.w = v[3] * inv;
    b.x = v[4] * inv; b.y = v[5] * inv; b.z = v[6] * inv; b.w = v[7] * inv;
    *(float4*)(p + c0) = a;
    *(float4*)(p + c1) = b;
}

__global__ void mulpack(const float* __restrict__ C1, const float* __restrict__ C2,
                        float* __restrict__ PK) {
    const size_t i = (size_t)blockIdx.x * 256 + threadIdx.x;
    if (i >= QSZ) return;
    const float v = C1[i] * C2[i];
    const int d = (int)(i & 63);
    const size_t r = i >> 6;
    const int s = (int)(r & (Sn - 1));
    const int bh = (int)(r >> 11);
    const int b = bh >> 4, h = bh & 15;
    PK[((size_t)(b * Sn + s)) * En + h * 64 + d] = v;
}

// ============================ launch ============================
extern "C" void kernel_launch(void* const* d_in, const int* in_sizes, int n_in,
                              void* d_out, int out_size) {
    const float* query = (const float*)d_in[0];
    const float* key   = (const float*)d_in[1];
    const float* value = (const float*)d_in[2];
    // d_in[3] = mask (causal tril, hardcoded)
    const float* Wf[7] = {
        (const float*)d_in[4],  (const float*)d_in[5], (const float*)d_in[6],
        (const float*)d_in[7],  (const float*)d_in[8], (const float*)d_in[9],
        (const float*)d_in[10]  // WQ1 WK1 WV1 WQ2 WK2 WV2 WO
    };

    float* out = (float*)d_out;
    float* w1  = out + (size_t)M_ROWS * En;
    float* w2  = w1 + WSZ;

    unsigned char* sc = nullptr;
    cudaGetSymbolAddress((void**)&sc, g_scratch);

    float* Y[6];
    for (int i = 0; i < 6; i++) Y[i] = (float*)(sc + (size_t)(16 * i) * MBb);
    float* QK[4];
    for (int i = 0; i < 4; i++) QK[i] = (float*)(sc + (size_t)(96 + 16 * i) * MBb);
    float* VT[2];
    for (int i = 0; i < 2; i++) VT[i] = (float*)(sc + (size_t)(160 + 16 * i) * MBb);
    float* CC[2];
    for (int i = 0; i < 2; i++) CC[i] = (float*)(sc + (size_t)(192 + 16 * i) * MBb);
    float* PK = (float*)(sc + (size_t)224 * MBb);

    const int SMEM_BIG = (128 + 128) * 72 * 2 * 2;   // 73728 (BN=128)
    const int SMEM_SML = (128 + 64) * 72 * 2 * 2;    // 55296 (BN=64)
    cudaFuncSetAttribute((const void*)&gemm_f32h<128, 2, 4>,
                         cudaFuncAttributeMaxDynamicSharedMemorySize, SMEM_BIG);
    cudaFuncSetAttribute((const void*)&gemm_f32h<64, 2, 4>,
                         cudaFuncAttributeMaxDynamicSharedMemorySize, SMEM_SML);
    cudaFuncSetAttribute((const void*)&gemm_f32h<64, 4, 2>,
                         cudaFuncAttributeMaxDynamicSharedMemorySize, SMEM_SML);

    // 1) projections: BN=64 -> 512 blocks (wave balance), prefetch inside
    const dim3 gproj(En / 64, M_ROWS / 128, 1);   // (16, 32)
    gemm_f32h<64,2,4><<<gproj, 256, SMEM_SML>>>(query, Wf[0], Y[0], 0,0,0, En, En, En, En, 1.f, 0);
    gemm_f32h<64,2,4><<<gproj, 256, SMEM_SML>>>(key,   Wf[1], Y[1], 0,0,0, En, En, En, En, 1.f, 0);
    gemm_f32h<64,2,4><<<gproj, 256, SMEM_SML>>>(value, Wf[2], Y[2], 0,0,0, En, En, En, En, 1.f, 0);
    gemm_f32h<64,2,4><<<gproj, 256, SMEM_SML>>>(query, Wf[3], Y[3], 0,0,0, En, En, En, En, 1.f, 0);
    gemm_f32h<64,2,4><<<gproj, 256, SMEM_SML>>>(key,   Wf[4], Y[4], 0,0,0, En, En, En, En, 1.f, 0);
    gemm_f32h<64,2,4><<<gproj, 256, SMEM_SML>>>(value, Wf[5], Y[5], 0,0,0, En, En, En, En, 1.f, 0);

    // 2) rope Q/K, transpose V
    const int re = Bn * Hn * Sn * 32;
    rope_f32<<<re / 256, 256>>>(Y[0], QK[0]);
    rope_f32<<<re / 256, 256>>>(Y[1], QK[1]);
    rope_f32<<<re / 256, 256>>>(Y[3], QK[2]);
    rope_f32<<<re / 256, 256>>>(Y[4], QK[3]);
    vtrans<<<dim3(Sn / 64, 1, Bn * Hn), 256>>>(Y[2], VT[0]);
    vtrans<<<dim3(Sn / 64, 1, Bn * Hn), 256>>>(Y[5], VT[1]);

    // 3) scores (causal tile-skip), softmax in place, ctx (causal kmax)
    const dim3 gsc(Sn / 128, Sn / 128, Bn * Hn);
    gemm_f32h<128,2,4><<<gsc, 256, SMEM_BIG>>>(
        QK[0], QK[1], w1, (long long)Sn * 64, (long long)Sn * 64, (long long)Sn * Sn,
        64, 64, Sn, 64, 0.125f, 1);
    softmax_reg<<<Bn * Hn * Sn, 256>>>(w1);
    gemm_f32h<64,4,2><<<dim3(1, Sn / 128, Bn * Hn), 256, SMEM_SML>>>(
        w1, VT[0], CC[0], (long long)Sn * Sn, (long long)64 * Sn, (long long)Sn * 64,
        Sn, Sn, 64, Sn, 1.f, 2);

    gemm_f32h<128,2,4><<<gsc, 256, SMEM_BIG>>>(
        QK[2], QK[3], w2, (long long)Sn * 64, (long long)Sn * 64, (long long)Sn * Sn,
        64, 64, Sn, 64, 0.125f, 1);
    softmax_reg<<<Bn * Hn * Sn, 256>>>(w2);
    gemm_f32h<64,4,2><<<dim3(1, Sn / 128, Bn * Hn), 256, SMEM_SML>>>(
        w2, VT[1], CC[1], (long long)Sn * Sn, (long long)64 * Sn, (long long)Sn * 64,
        Sn, Sn, 64, Sn, 1.f, 2);

    // 4) multiply+pack, output projection
    mulpack<<<(unsigned)((QSZ + 255) / 256), 256>>>(CC[0], CC[1], PK);
    gemm_f32h<64,2,4><<<gproj, 256, SMEM_SML>>>(PK, Wf[6], out, 0,0,0, En, En, En, En, 1.f, 0);
}

// round 7
// speedup vs baseline: 1.8098x; 1.0561x over previous
#include <cuda_runtime.h>
#include <cuda_fp16.h>
#include <cstdint>
#include <float.h>
#include <math.h>

#define Bn 2
#define Sn 2048
#define Hn 16
#define Dn 64
#define En 1024
#define M_ROWS (Bn*Sn)
#define QSZ ((size_t)Bn*Hn*Sn*Dn)
#define WSZ ((size_t)Bn*Hn*Sn*Sn)
#define MBb (1024ull*1024ull)

// scratch (MB offsets): Y[6]=16i, QK[4]=96+16i, VT[2]=160+16i, CC[2]=192+16i, PK=224
__device__ __align__(1024) unsigned char g_scratch[240 * 1024 * 1024];

struct PtrBatch {
    const float* A[8];
    const float* B[8];
    float* C[8];
};

__device__ __forceinline__ uint32_t packh2(float a, float b) {
    __half2 h = __halves2half2(__float2half_rn(a), __float2half_rn(b));
    return *(uint32_t*)&h;
}
__device__ __forceinline__ void ldm_x4(uint32_t* r, uint32_t addr) {
    asm volatile("ldmatrix.sync.aligned.m8n8.x4.shared.b16 {%0,%1,%2,%3}, [%4];"
                 : "=r"(r[0]), "=r"(r[1]), "=r"(r[2]), "=r"(r[3]) : "r"(addr));
}
__device__ __forceinline__ void ldm_x2(uint32_t* r, uint32_t addr) {
    asm volatile("ldmatrix.sync.aligned.m8n8.x2.shared.b16 {%0,%1}, [%2];"
                 : "=r"(r[0]), "=r"(r[1]) : "r"(addr));
}
__device__ __forceinline__ void mma16816(float* d, const uint32_t* a, const uint32_t* b) {
    asm volatile(
        "mma.sync.aligned.m16n8k16.row.col.f32.f16.f16.f32 "
        "{%0,%1,%2,%3}, {%4,%5,%6,%7}, {%8,%9}, {%0,%1,%2,%3};"
        : "+f"(d[0]), "+f"(d[1]), "+f"(d[2]), "+f"(d[3])
        : "r"(a[0]), "r"(a[1]), "r"(a[2]), "r"(a[3]), "r"(b[0]), "r"(b[1]));
}

// ============================================================================
// f32-in GEMM on fp16 mma.sync: in-kernel hi/lo split, 3 combos, ldmatrix
// fragments, double-buffered smem (1 sync per chunk), register prefetch.
// C[m,n] = scale * sum_k A[m,k]*B[n,k]. BM=128, chunk K=64.
// MODE: 0 none, 1 causal tile-skip, 2 causal kmax.
// ============================================================================
template<int BN, int WR, int WCn, int MODE>
__global__ void __launch_bounds__(256) gemm2(
    PtrBatch bt, int zShift,
    long long sAz, long long sBz, long long sCz,
    int lda, int ldb, int ldc, int Kblk, float scale)
{
    constexpr int BM = 128, STR = 72;
    constexpr int THREADS = 256;
    constexpr int WM = BM / WR, WN = BN / WCn;
    constexpr int MF = WM / 16, NF = WN / 8;
    constexpr int ALD = BM * 64 / (4 * THREADS);   // 8
    constexpr int BLD = BN * 64 / (4 * THREADS);   // 8 or 4
    constexpr int PBUF = (2 * BM + 2 * BN) * STR;  // halves per buffer

    const int task = blockIdx.z >> zShift;
    const int zb = blockIdx.z & ((1 << zShift) - 1);
    const int m0 = blockIdx.y * BM;
    const int n0 = blockIdx.x * BN;
    if (MODE == 1 && n0 > m0 + BM - 1) return;
    const int kmax = (MODE == 2) ? min(Kblk, m0 + BM) : Kblk;
    const int nk = kmax >> 6;

    const float* A = bt.A[task] + (size_t)zb * sAz;
    const float* B = bt.B[task] + (size_t)zb * sBz;
    float* C = bt.C[task] + (size_t)zb * sCz;

    extern __shared__ __align__(16) half smh[];

    const int tid = threadIdx.x;
    const int lane = tid & 31;
    const int w = tid >> 5;
    const int wm = (w / WCn) * WM;
    const int wn = (w % WCn) * WN;

    // ldmatrix per-lane offsets
    const int g = lane >> 3, r8 = lane & 7;
    const int aRow = r8 + ((g & 1) ? 8 : 0), aCol = (g & 2) ? 8 : 0;
    const int bCol = ((lane >> 3) & 1) ? 8 : 0;
    const uint32_t aOffB = (uint32_t)(((wm + aRow) * STR + aCol) * 2);
    const uint32_t bOffB = (uint32_t)(((wn + r8) * STR + bCol) * 2);

    float acc[MF][NF][4] = {};
    float4 pa[ALD], pb[BLD];

    auto gload = [&](int kc) {
        #pragma unroll
        for (int i = 0; i < ALD; i++) {
            const int u = i * THREADS + tid;
            pa[i] = *(const float4*)(A + (size_t)(m0 + (u >> 4)) * lda + kc * 64 + (u & 15) * 4);
        }
        #pragma unroll
        for (int i = 0; i < BLD; i++) {
            const int u = i * THREADS + tid;
            pb[i] = *(const float4*)(B + (size_t)(n0 + (u >> 4)) * ldb + kc * 64 + (u & 15) * 4);
        }
    };

    auto cvt_store = [&](int b) {
        half* Ah = smh + b * PBUF;
        half* Al = Ah + BM * STR;
        half* Bh = Al + BM * STR;
        half* Bl = Bh + BN * STR;
        #pragma unroll
        for (int i = 0; i < ALD; i++) {
            const int u = i * THREADS + tid;
            const int row = u >> 4, c4 = (u & 15) * 4;
            const float4 v = pa[i];
            const float hx = __half2float(__float2half_rn(v.x));
            const float hy = __half2float(__float2half_rn(v.y));
            const float hz = __half2float(__float2half_rn(v.z));
            const float hw = __half2float(__float2half_rn(v.w));
            uint2 Hi = { packh2(v.x, v.y), packh2(v.z, v.w) };
            uint2 Lo = { packh2(v.x - hx, v.y - hy), packh2(v.z - hz, v.w - hw) };
            *(uint2*)&Ah[row * STR + c4] = Hi;
            *(uint2*)&Al[row * STR + c4] = Lo;
        }
        #pragma unroll
        for (int i = 0; i < BLD; i++) {
            const int u = i * THREADS + tid;
            const int row = u >> 4, c4 = (u & 15) * 4;
            const float4 v = pb[i];
            const float hx = __half2float(__float2half_rn(v.x));
            const float hy = __half2float(__float2half_rn(v.y));
            const float hz = __half2float(__float2half_rn(v.z));
            const float hw = __half2float(__float2half_rn(v.w));
            uint2 Hi = { packh2(v.x, v.y), packh2(v.z, v.w) };
            uint2 Lo = { packh2(v.x - hx, v.y - hy), packh2(v.z - hz, v.w - hw) };
            *(uint2*)&Bh[row * STR + c4] = Hi;
            *(uint2*)&Bl[row * STR + c4] = Lo;
        }
    };

    gload(0);
    cvt_store(0);
    if (nk > 1) gload(1);

    for (int kc = 0; kc < nk; kc++) {
        __syncthreads();
        const int b = kc & 1;
        const uint32_t AhB = (uint32_t)__cvta_generic_to_shared(smh + b * PBUF);
        const uint32_t AlB = AhB + BM * STR * 2;
        const uint32_t BhB = AlB + BM * STR * 2;
        const uint32_t BlB = BhB + BN * STR * 2;

        #pragma unroll
        for (int ks = 0; ks < 4; ks++) {
            uint32_t ah[MF][4], al[MF][4], bh[NF][2], bl[NF][2];
            #pragma unroll
            for (int mf = 0; mf < MF; mf++) {
                const uint32_t off = aOffB + (uint32_t)((mf * 16 * STR + ks * 16) * 2);
                ldm_x4(ah[mf], AhB + off);
                ldm_x4(al[mf], AlB + off);
            }
            #pragma unroll
            for (int nf = 0; nf < NF; nf++) {
                const uint32_t off = bOffB + (uint32_t)((nf * 8 * STR + ks * 16) * 2);
                ldm_x2(bh[nf], BhB + off);
                ldm_x2(bl[nf], BlB + off);
            }
            #pragma unroll
            for (int mf = 0; mf < MF; mf++)
                #pragma unroll
                for (int nf = 0; nf < NF; nf++)
                    mma16816(acc[mf][nf], ah[mf], bh[nf]);
            #pragma unroll
            for (int mf = 0; mf < MF; mf++)
                #pragma unroll
                for (int nf = 0; nf < NF; nf++)
                    mma16816(acc[mf][nf], ah[mf], bl[nf]);
            #pragma unroll
            for (int mf = 0; mf < MF; mf++)
                #pragma unroll
                for (int nf = 0; nf < NF; nf++)
                    mma16816(acc[mf][nf], al[mf], bh[nf]);
        }

        if (kc + 1 < nk) {
            cvt_store((kc + 1) & 1);
            if (kc + 2 < nk) gload(kc + 2);
        }
    }

    #pragma unroll
    for (int mf = 0; mf < MF; mf++) {
        const int row = m0 + wm + mf * 16 + (lane >> 2);
        #pragma unroll
        for (int nf = 0; nf < NF; nf++) {
            const int col = n0 + wn + nf * 8 + (lane & 3) * 2;
            float2 v0 = { acc[mf][nf][0] * scale, acc[mf][nf][1] * scale };
            float2 v1 = { acc[mf][nf][2] * scale, acc[mf][nf][3] * scale };
            *(float2*)&C[(size_t)row * ldc + col] = v0;
            *(float2*)&C[(size_t)(row + 8) * ldc + col] = v1;
        }
    }
}

// ============================ aux kernels ============================
struct RopeB { const float* src[4]; float* dst[4]; };
__global__ void rope_b(RopeB rb) {
    const int i = blockIdx.x * 256 + threadIdx.x;
    const float* Y = rb.src[blockIdx.y];
    float* Qr = rb.dst[blockIdx.y];
    const int j = i & 31;
    const int s = (i >> 5) & (Sn - 1);
    const int bh = i >> 16;
    const int b = bh >> 4, h = bh & 15;
    const float* yr = Y + ((size_t)(b * Sn + s)) * En + h * 64;
    const float x1 = yr[j], x2 = yr[j + 32];
    const double invf = pow(10000.0, -(double)j / 32.0);
    const float ang = (float)((double)s * invf);
    const float sv = sinf(ang), cv = cosf(ang);
    float* o = Qr + ((size_t)bh * Sn + s) * 64;
    o[j]      = x1 * cv - x2 * sv;
    o[j + 32] = x1 * sv + x2 * cv;
}

struct VtB { const float* src[2]; float* dst[2]; };
__global__ void vtrans_b(VtB vb) {
    __shared__ float t[64][65];
    const int task = blockIdx.z >> 5;
    const int bh = blockIdx.z & 31;
    const float* Yv = vb.src[task];
    float* VT = vb.dst[task];
    const int s0 = blockIdx.x * 64;
    const int b = bh >> 4, h = bh & 15;
    const int tid = threadIdx.x;
    #pragma unroll
    for (int i = 0; i < 16; i++) {
        const int u = i * 256 + tid;
        const int s = u >> 6, d = u & 63;
        t[s][d] = Yv[((size_t)(b * Sn + s0 + s)) * En + h * 64 + d];
    }
    __syncthreads();
    #pragma unroll
    for (int i = 0; i < 16; i++) {
        const int u = i * 256 + tid;
        const int d = u >> 6, s = u & 63;
        VT[((size_t)bh * 64 + d) * Sn + s0 + s] = t[s][d];
    }
}

// register-cached causal softmax in place; grid (rows, 2)
__global__ void softmax_b(float* __restrict__ wa, float* __restrict__ wb) {
    float* W = blockIdx.y ? wb : wa;
    const int row = blockIdx.x;
    const int q = row & (Sn - 1);
    float* p = W + (size_t)row * Sn;
    const int tid = threadIdx.x;
    const int c0 = tid * 4, c1 = 1024 + tid * 4;
    __shared__ float red[8];

    float4 a = *(float4*)(p + c0);
    float4 b = *(float4*)(p + c1);
    float v[8] = { a.x, a.y, a.z, a.w, b.x, b.y, b.z, b.w };

    float m = -1e30f;
    #pragma unroll
    for (int j = 0; j < 8; j++) {
        const int col = (j < 4) ? (c0 + j) : (c1 + j - 4);
        if (col <= q) m = fmaxf(m, v[j]);
    }
    #pragma unroll
    for (int o = 16; o; o >>= 1) m = fmaxf(m, __shfl_xor_sync(0xffffffffu, m, o));
    if ((tid & 31) == 0) red[tid >> 5] = m;
    __syncthreads();
    if (tid < 32) {
        float mm = (tid < 8) ? red[tid] : -1e30f;
        #pragma unroll
        for (int o = 4; o; o >>= 1) mm = fmaxf(mm, __shfl_xor_sync(0xffffffffu, mm, o));
        if (tid == 0) red[0] = mm;
    }
    __syncthreads();
    m = red[0];
    __syncthreads();

    float sum = 0.f;
    #pragma unroll
    for (int j = 0; j < 8; j++) {
        const int col = (j < 4) ? (c0 + j) : (c1 + j - 4);
        v[j] = (col <= q) ? expf(v[j] - m) : 0.f;
        sum += v[j];
    }
    #pragma unroll
    for (int o = 16; o; o >>= 1) sum += __shfl_xor_sync(0xffffffffu, sum, o);
    if ((tid & 31) == 0) red[tid >> 5] = sum;
    __syncthreads();
    if (tid < 32) {
        float s = (tid < 8) ? red[tid] : 0.f;
        #pragma unroll
        for (int o = 4; o; o >>= 1) s += __shfl_xor_sync(0xffffffffu, s, o);
        if (tid == 0) red[0] = s;
    }
    __syncthreads();
    const float inv = 1.0f / red[0];

    a.x = v[0] * inv; a.y = v[1] * inv; a.z = v[2] * inv; a.w = v[3] * inv;
    b.x = v[4] * inv; b.y = v[5] * inv; b.z = v[6] * inv; b.w = v[7] * inv;
    *(float4*)(p + c0) = a;
    *(float4*)(p + c1) = b;
}

__global__ void mulpack(const float* __restrict__ C1, const float* __restrict__ C2,
                        float* __restrict__ PK) {
    const size_t i = (size_t)blockIdx.x * 256 + threadIdx.x;
    if (i >= QSZ) return;
    const float v = C1[i] * C2[i];
    const int d = (int)(i & 63);
    const size_t r = i >> 6;
    const int s = (int)(r & (Sn - 1));
    const int bh = (int)(r >> 11);
    const int b = bh >> 4, h = bh & 15;
    PK[((size_t)(b * Sn + s)) * En + h * 64 + d] = v;
}

// ============================ launch ============================
extern "C" void kernel_launch(void* const* d_in, const int* in_sizes, int n_in,
                              void* d_out, int out_size) {
    const float* query = (const float*)d_in[0];
    const float* key   = (const float*)d_in[1];
    const float* value = (const float*)d_in[2];
    // d_in[3] = mask (causal tril, hardcoded)
    const float* Wf[7] = {
        (const float*)d_in[4],  (const float*)d_in[5], (const float*)d_in[6],
        (const float*)d_in[7],  (const float*)d_in[8], (const float*)d_in[9],
        (const float*)d_in[10]  // WQ1 WK1 WV1 WQ2 WK2 WV2 WO
    };

    float* out = (float*)d_out;
    float* w1  = out + (size_t)M_ROWS * En;
    float* w2  = w1 + WSZ;

    unsigned char* sc = nullptr;
    cudaGetSymbolAddress((void**)&sc, g_scratch);

    float* Y[6];
    for (int i = 0; i < 6; i++) Y[i] = (float*)(sc + (size_t)(16 * i) * MBb);
    float* QK[4];
    for (int i = 0; i < 4; i++) QK[i] = (float*)(sc + (size_t)(96 + 16 * i) * MBb);
    float* VT[2];
    for (int i = 0; i < 2; i++) VT[i] = (float*)(sc + (size_t)(160 + 16 * i) * MBb);
    float* CC[2];
    for (int i = 0; i < 2; i++) CC[i] = (float*)(sc + (size_t)(192 + 16 * i) * MBb);
    float* PK = (float*)(sc + (size_t)224 * MBb);

    const int SMEM_128 = (2 * 128 + 2 * 128) * 72 * 2 * 2; // 147456
    const int SMEM_64  = (2 * 128 + 2 * 64) * 72 * 2 * 2;  // 110592
    cudaFuncSetAttribute((const void*)&gemm2<64, 2, 4, 0>,
                         cudaFuncAttributeMaxDynamicSharedMemorySize, SMEM_64);
    cudaFuncSetAttribute((const void*)&gemm2<128, 2, 4, 1>,
                         cudaFuncAttributeMaxDynamicSharedMemorySize, SMEM_128);
    cudaFuncSetAttribute((const void*)&gemm2<64, 4, 2, 2>,
                         cudaFuncAttributeMaxDynamicSharedMemorySize, SMEM_64);

    // 1) six projections in one launch (z = 0..5)
    PtrBatch bp = {};
    bp.A[0] = query; bp.A[1] = key; bp.A[2] = value;
    bp.A[3] = query; bp.A[4] = key; bp.A[5] = value;
    for (int i = 0; i < 6; i++) { bp.B[i] = Wf[i]; bp.C[i] = Y[i]; }
    gemm2<64, 2, 4, 0><<<dim3(En / 64, M_ROWS / 128, 6), 256, SMEM_64>>>(
        bp, 0, 0, 0, 0, En, En, En, En, 1.f);

    // 2) rope (4 tensors, one launch) + V transpose (2 tensors, one launch)
    RopeB rb = {};
    rb.src[0] = Y[0]; rb.dst[0] = QK[0];
    rb.src[1] = Y[1]; rb.dst[1] = QK[1];
    rb.src[2] = Y[3]; rb.dst[2] = QK[2];
    rb.src[3] = Y[4]; rb.dst[3] = QK[3];
    rope_b<<<dim3((Bn * Hn * Sn * 32) / 256, 4), 256>>>(rb);
    VtB vb = {};
    vb.src[0] = Y[2]; vb.dst[0] = VT[0];
    vb.src[1] = Y[5]; vb.dst[1] = VT[1];
    vtrans_b<<<dim3(Sn / 64, 1, 64), 256>>>(vb);

    // 3) scores both heads (z = 64: task=z>>5, bh=z&31), causal tile-skip
    PtrBatch bs = {};
    bs.A[0] = QK[0]; bs.B[0] = QK[1]; bs.C[0] = w1;
    bs.A[1] = QK[2]; bs.B[1] = QK[3]; bs.C[1] = w2;
    gemm2<128, 2, 4, 1><<<dim3(Sn / 128, Sn / 128, 64), 256, SMEM_128>>>(
        bs, 5, (long long)Sn * 64, (long long)Sn * 64, (long long)Sn * Sn,
        64, 64, Sn, 64, 0.125f);

    // 4) softmax both heads
    softmax_b<<<dim3(Bn * Hn * Sn, 2), 256>>>(w1, w2);

    // 5) ctx both heads, causal kmax
    PtrBatch bc = {};
    bc.A[0] = w1; bc.B[0] = VT[0]; bc.C[0] = CC[0];
    bc.A[1] = w2; bc.B[1] = VT[1]; bc.C[1] = CC[1];
    gemm2<64, 4, 2, 2><<<dim3(1, Sn / 128, 64), 256, SMEM_64>>>(
        bc, 5, (long long)Sn * Sn, (long long)64 * Sn, (long long)Sn * 64,
        Sn, Sn, 64, Sn, 1.f);

    // 6) multiply+pack, output projection
    mulpack<<<(unsigned)((QSZ + 255) / 256), 256>>>(CC[0], CC[1], PK);
    PtrBatch bo = {};
    bo.A[0] = PK; bo.B[0] = Wf[6]; bo.C[0] = out;
    gemm2<64, 2, 4, 0><<<dim3(En / 64, M_ROWS / 128, 1), 256, SMEM_64>>>(
        bo, 0, 0, 0, 0, En, En, En, En, 1.f);
}

// round 8
// speedup vs baseline: 1.8916x; 1.0452x over previous
#include <cuda_runtime.h>
#include <cuda_fp16.h>
#include <cstdint>
#include <float.h>
#include <math.h>

#define Bn 2
#define Sn 2048
#define Hn 16
#define Dn 64
#define En 1024
#define M_ROWS (Bn*Sn)
#define QSZ ((size_t)Bn*Hn*Sn*Dn)
#define WSZ ((size_t)Bn*Hn*Sn*Sn)
#define MBb (1024ull*1024ull)

// scratch (MB offsets): Y[6]=16i, QK[4]=96+16i, VT[2]=160+16i, CC[2]=192+16i
__device__ __align__(1024) unsigned char g_scratch[224 * 1024 * 1024];

struct PtrBatch {
    const float* A[8];
    const float* A2[8];   // optional second A operand (elementwise multiply fuse)
    const float* B[8];
    float* C[8];
};

__device__ __forceinline__ uint32_t packh2(float a, float b) {
    __half2 h = __halves2half2(__float2half_rn(a), __float2half_rn(b));
    return *(uint32_t*)&h;
}
__device__ __forceinline__ void ldm_x4(uint32_t* r, uint32_t addr) {
    asm volatile("ldmatrix.sync.aligned.m8n8.x4.shared.b16 {%0,%1,%2,%3}, [%4];"
                 : "=r"(r[0]), "=r"(r[1]), "=r"(r[2]), "=r"(r[3]) : "r"(addr));
}
__device__ __forceinline__ void ldm_x2(uint32_t* r, uint32_t addr) {
    asm volatile("ldmatrix.sync.aligned.m8n8.x2.shared.b16 {%0,%1}, [%2];"
                 : "=r"(r[0]), "=r"(r[1]) : "r"(addr));
}
__device__ __forceinline__ void mma16816(float* d, const uint32_t* a, const uint32_t* b) {
    asm volatile(
        "mma.sync.aligned.m16n8k16.row.col.f32.f16.f16.f32 "
        "{%0,%1,%2,%3}, {%4,%5,%6,%7}, {%8,%9}, {%0,%1,%2,%3};"
        : "+f"(d[0]), "+f"(d[1]), "+f"(d[2]), "+f"(d[3])
        : "r"(a[0]), "r"(a[1]), "r"(a[2]), "r"(a[3]), "r"(b[0]), "r"(b[1]));
}
__device__ __forceinline__ void splitv(const float4 v, uint2& Hi, uint2& Lo) {
    const float hx = __half2float(__float2half_rn(v.x));
    const float hy = __half2float(__float2half_rn(v.y));
    const float hz = __half2float(__float2half_rn(v.z));
    const float hw = __half2float(__float2half_rn(v.w));
    Hi = { packh2(v.x, v.y), packh2(v.z, v.w) };
    Lo = { packh2(v.x - hx, v.y - hy), packh2(v.z - hz, v.w - hw) };
}

// ============================================================================
// Generic f32-in GEMM on fp16 mma.sync: hi/lo split, 3 combos, ldmatrix,
// double-buffered smem, register prefetch.  C = scale * A @ B^T.
// MODE: 0 none, 2 causal kmax.  FUSE: A-load = A[.]*A2[.] with bh index xform.
// ============================================================================
template<int BN, int WR, int WCn, int MODE, int FUSE>
__global__ void __launch_bounds__(256) gemm2(
    PtrBatch bt, int zShift,
    long long sAz, long long sBz, long long sCz,
    int lda, int ldb, int ldc, int Kblk, float scale)
{
    constexpr int BM = 128, STR = 72;
    constexpr int THREADS = 256;
    constexpr int WM = BM / WR, WN = BN / WCn;
    constexpr int MF = WM / 16, NF = WN / 8;
    constexpr int ALD = BM * 64 / (4 * THREADS);
    constexpr int BLD = BN * 64 / (4 * THREADS);
    constexpr int PBUF = (2 * BM + 2 * BN) * STR;

    const int task = blockIdx.z >> zShift;
    const int zb = blockIdx.z & ((1 << zShift) - 1);
    const int m0 = blockIdx.y * BM;
    const int n0 = blockIdx.x * BN;
    const int kmax = (MODE == 2) ? min(Kblk, m0 + BM) : Kblk;
    const int nk = kmax >> 6;

    const float* A = bt.A[task] + (size_t)zb * sAz;
    const float* A2 = FUSE ? bt.A2[task] : nullptr;
    const float* B = bt.B[task] + (size_t)zb * sBz;
    float* C = bt.C[task] + (size_t)zb * sCz;

    extern __shared__ __align__(16) half smh[];

    const int tid = threadIdx.x;
    const int lane = tid & 31;
    const int w = tid >> 5;
    const int wm = (w / WCn) * WM;
    const int wn = (w % WCn) * WN;

    const int g = lane >> 3, r8 = lane & 7;
    const int aRow = r8 + ((g & 1) ? 8 : 0), aCol = (g & 2) ? 8 : 0;
    const uint32_t aOffB = (uint32_t)(((wm + aRow) * STR + aCol) * 2);
    const int bCol = ((lane >> 3) & 1) ? 8 : 0;
    const uint32_t bOffB = (uint32_t)(((wn + r8) * STR + bCol) * 2);

    float acc[MF][NF][4] = {};
    float4 pa[ALD], pb[BLD];

    auto gload = [&](int kc) {
        #pragma unroll
        for (int i = 0; i < ALD; i++) {
            const int u = i * THREADS + tid;
            if (FUSE) {
                const int row = m0 + (u >> 4);
                const int b = row >> 11, s = row & (Sn - 1);
                const size_t idx = (((size_t)(b * Hn + kc)) * Sn + s) * 64 + (u & 15) * 4;
                const float4 x = *(const float4*)(A + idx);
                const float4 y = *(const float4*)(A2 + idx);
                pa[i] = { x.x * y.x, x.y * y.y, x.z * y.z, x.w * y.w };
            } else {
                pa[i] = *(const float4*)(A + (size_t)(m0 + (u >> 4)) * lda + kc * 64 + (u & 15) * 4);
            }
        }
        #pragma unroll
        for (int i = 0; i < BLD; i++) {
            const int u = i * THREADS + tid;
            pb[i] = *(const float4*)(B + (size_t)(n0 + (u >> 4)) * ldb + kc * 64 + (u & 15) * 4);
        }
    };

    auto cvt_store = [&](int b) {
        half* Ah = smh + b * PBUF;
        half* Al = Ah + BM * STR;
        half* Bh = Al + BM * STR;
        half* Bl = Bh + BN * STR;
        #pragma unroll
        for (int i = 0; i < ALD; i++) {
            const int u = i * THREADS + tid;
            uint2 Hi, Lo;
            splitv(pa[i], Hi, Lo);
            *(uint2*)&Ah[(u >> 4) * STR + (u & 15) * 4] = Hi;
            *(uint2*)&Al[(u >> 4) * STR + (u & 15) * 4] = Lo;
        }
        #pragma unroll
        for (int i = 0; i < BLD; i++) {
            const int u = i * THREADS + tid;
            uint2 Hi, Lo;
            splitv(pb[i], Hi, Lo);
            *(uint2*)&Bh[(u >> 4) * STR + (u & 15) * 4] = Hi;
            *(uint2*)&Bl[(u >> 4) * STR + (u & 15) * 4] = Lo;
        }
    };

    gload(0);
    cvt_store(0);
    if (nk > 1) gload(1);

    for (int kc = 0; kc < nk; kc++) {
        __syncthreads();
        const int b = kc & 1;
        const uint32_t AhB = (uint32_t)__cvta_generic_to_shared(smh + b * PBUF);
        const uint32_t AlB = AhB + BM * STR * 2;
        const uint32_t BhB = AlB + BM * STR * 2;
        const uint32_t BlB = BhB + BN * STR * 2;

        #pragma unroll
        for (int ks = 0; ks < 4; ks++) {
            uint32_t ah[MF][4], al[MF][4], bh[NF][2], bl[NF][2];
            #pragma unroll
            for (int mf = 0; mf < MF; mf++) {
                const uint32_t off = aOffB + (uint32_t)((mf * 16 * STR + ks * 16) * 2);
                ldm_x4(ah[mf], AhB + off);
                ldm_x4(al[mf], AlB + off);
            }
            #pragma unroll
            for (int nf = 0; nf < NF; nf++) {
                const uint32_t off = bOffB + (uint32_t)((nf * 8 * STR + ks * 16) * 2);
                ldm_x2(bh[nf], BhB + off);
                ldm_x2(bl[nf], BlB + off);
            }
            #pragma unroll
            for (int mf = 0; mf < MF; mf++)
                #pragma unroll
                for (int nf = 0; nf < NF; nf++)
                    mma16816(acc[mf][nf], ah[mf], bh[nf]);
            #pragma unroll
            for (int mf = 0; mf < MF; mf++)
                #pragma unroll
                for (int nf = 0; nf < NF; nf++)
                    mma16816(acc[mf][nf], ah[mf], bl[nf]);
            #pragma unroll
            for (int mf = 0; mf < MF; mf++)
                #pragma unroll
                for (int nf = 0; nf < NF; nf++)
                    mma16816(acc[mf][nf], al[mf], bh[nf]);
        }

        if (kc + 1 < nk) {
            cvt_store((kc + 1) & 1);
            if (kc + 2 < nk) gload(kc + 2);
        }
    }

    #pragma unroll
    for (int mf = 0; mf < MF; mf++) {
        const int row = m0 + wm + mf * 16 + (lane >> 2);
        #pragma unroll
        for (int nf = 0; nf < NF; nf++) {
            const int col = n0 + wn + nf * 8 + (lane & 3) * 2;
            float2 v0 = { acc[mf][nf][0] * scale, acc[mf][nf][1] * scale };
            float2 v1 = { acc[mf][nf][2] * scale, acc[mf][nf][3] * scale };
            *(float2*)&C[(size_t)row * ldc + col] = v0;
            *(float2*)&C[(size_t)(row + 8) * ldc + col] = v1;
        }
    }
}

// ============================================================================
// Scores kernel: K=64 (one chunk). A (Q tile) resident; loop NSUB n-subtiles
// of 128 with double-buffered B and register prefetch. Causal sub-tile skip.
// ============================================================================
template<int NSUB>
__global__ void __launch_bounds__(256) scores_nl(
    PtrBatch bt, float scale)
{
    constexpr int BM = 128, BNS = 128, STR = 72;
    constexpr int THREADS = 256;
    constexpr int WR = 2, WCn = 4;
    constexpr int WM = BM / WR, WN = BNS / WCn;   // 64, 32
    constexpr int MF = WM / 16, NF = WN / 8;      // 4, 4
    constexpr int ALD = 8, BLD = 8;

    const int task = blockIdx.z >> 5;
    const int bh = blockIdx.z & 31;
    const int m0 = blockIdx.y * BM;
    const int nbase = blockIdx.x * BNS * NSUB;
    if (nbase > m0 + BM - 1) return;
    const int nActive = min(NSUB, (m0 + BM - 1 - nbase) / BNS + 1);

    const float* A = bt.A[task] + (size_t)bh * Sn * 64;
    const float* B = bt.B[task] + (size_t)bh * Sn * 64;
    float* C = bt.C[task] + (size_t)bh * Sn * Sn;

    extern __shared__ __align__(16) half smh[];
    half* Ah = smh;                        // 128*72
    half* Al = Ah + BM * STR;
    half* Bbuf = Al + BM * STR;            // 2 buffers of (Bh,Bl)
    constexpr int BBUF = 2 * BNS * STR;

    const int tid = threadIdx.x;
    const int lane = tid & 31;
    const int w = tid >> 5;
    const int wm = (w / WCn) * WM;
    const int wn = (w % WCn) * WN;

    const int g = lane >> 3, r8 = lane & 7;
    const int aRow = r8 + ((g & 1) ? 8 : 0), aCol = (g & 2) ? 8 : 0;
    const uint32_t aOffB = (uint32_t)(((wm + aRow) * STR + aCol) * 2);
    const int bCol = ((lane >> 3) & 1) ? 8 : 0;
    const uint32_t bOffB = (uint32_t)(((wn + r8) * STR + bCol) * 2);

    float4 pa[ALD], pb[BLD];

    // load + convert A tile (resident for whole block)
    #pragma unroll
    for (int i = 0; i < ALD; i++) {
        const int u = i * THREADS + tid;
        pa[i] = *(const float4*)(A + (size_t)(m0 + (u >> 4)) * 64 + (u & 15) * 4);
    }
    #pragma unroll
    for (int i = 0; i < ALD; i++) {
        const int u = i * THREADS + tid;
        uint2 Hi, Lo;
        splitv(pa[i], Hi, Lo);
        *(uint2*)&Ah[(u >> 4) * STR + (u & 15) * 4] = Hi;
        *(uint2*)&Al[(u >> 4) * STR + (u & 15) * 4] = Lo;
    }

    auto gloadB = [&](int nn) {
        const int n0 = nbase + nn * BNS;
        #pragma unroll
        for (int i = 0; i < BLD; i++) {
            const int u = i * THREADS + tid;
            pb[i] = *(const float4*)(B + (size_t)(n0 + (u >> 4)) * 64 + (u & 15) * 4);
        }
    };
    auto cvtB = [&](int buf) {
        half* Bh = Bbuf + buf * BBUF;
        half* Bl = Bh + BNS * STR;
        #pragma unroll
        for (int i = 0; i < BLD; i++) {
            const int u = i * THREADS + tid;
            uint2 Hi, Lo;
            splitv(pb[i], Hi, Lo);
            *(uint2*)&Bh[(u >> 4) * STR + (u & 15) * 4] = Hi;
            *(uint2*)&Bl[(u >> 4) * STR + (u & 15) * 4] = Lo;
        }
    };

    gloadB(0);
    cvtB(0);
    __syncthreads();

    const uint32_t AhB = (uint32_t)__cvta_generic_to_shared(Ah);
    const uint32_t AlB = AhB + BM * STR * 2;

    for (int nn = 0; nn < nActive; nn++) {
        if (nn + 1 < nActive) gloadB(nn + 1);

        const uint32_t BhB = (uint32_t)__cvta_generic_to_shared(Bbuf + (nn & 1) * BBUF);
        const uint32_t BlB = BhB + BNS * STR * 2;

        float acc[MF][NF][4] = {};
        #pragma unroll
        for (int ks = 0; ks < 4; ks++) {
            uint32_t ah[MF][4], al[MF][4], bh[NF][2], bl[NF][2];
            #pragma unroll
            for (int mf = 0; mf < MF; mf++) {
                const uint32_t off = aOffB + (uint32_t)((mf * 16 * STR + ks * 16) * 2);
                ldm_x4(ah[mf], AhB + off);
                ldm_x4(al[mf], AlB + off);
            }
            #pragma unroll
            for (int nf = 0; nf < NF; nf++) {
                const uint32_t off = bOffB + (uint32_t)((nf * 8 * STR + ks * 16) * 2);
                ldm_x2(bh[nf], BhB + off);
                ldm_x2(bl[nf], BlB + off);
            }
            #pragma unroll
            for (int mf = 0; mf < MF; mf++)
                #pragma unroll
                for (int nf = 0; nf < NF; nf++)
                    mma16816(acc[mf][nf], ah[mf], bh[nf]);
            #pragma unroll
            for (int mf = 0; mf < MF; mf++)
                #pragma unroll
                for (int nf = 0; nf < NF; nf++)
                    mma16816(acc[mf][nf], ah[mf], bl[nf]);
            #pragma unroll
            for (int mf = 0; mf < MF; mf++)
                #pragma unroll
                for (int nf = 0; nf < NF; nf++)
                    mma16816(acc[mf][nf], al[mf], bh[nf]);
        }

        // epilogue for this n-subtile
        const int n0 = nbase + nn * BNS;
        #pragma unroll
        for (int mf = 0; mf < MF; mf++) {
            const int row = m0 + wm + mf * 16 + (lane >> 2);
            #pragma unroll
            for (int nf = 0; nf < NF; nf++) {
                const int col = n0 + wn + nf * 8 + (lane & 3) * 2;
                float2 v0 = { acc[mf][nf][0] * scale, acc[mf][nf][1] * scale };
                float2 v1 = { acc[mf][nf][2] * scale, acc[mf][nf][3] * scale };
                *(float2*)&C[(size_t)row * Sn + col] = v0;
                *(float2*)&C[(size_t)(row + 8) * Sn + col] = v1;
            }
        }

        if (nn + 1 < nActive) {
            cvtB((nn + 1) & 1);
            __syncthreads();
        }
    }
}

// ============================ aux kernels ============================
struct RopeB { const float* src[4]; float* dst[4]; };
__global__ void rope_b(RopeB rb) {
    const int i = blockIdx.x * 256 + threadIdx.x;
    const float* Y = rb.src[blockIdx.y];
    float* Qr = rb.dst[blockIdx.y];
    const int j = i & 31;
    const int s = (i >> 5) & (Sn - 1);
    const int bh = i >> 16;
    const int b = bh >> 4, h = bh & 15;
    const float* yr = Y + ((size_t)(b * Sn + s)) * En + h * 64;
    const float x1 = yr[j], x2 = yr[j + 32];
    const double invf = pow(10000.0, -(double)j / 32.0);
    const float ang = (float)((double)s * invf);
    const float sv = sinf(ang), cv = cosf(ang);
    float* o = Qr + ((size_t)bh * Sn + s) * 64;
    o[j]      = x1 * cv - x2 * sv;
    o[j + 32] = x1 * sv + x2 * cv;
}

struct VtB { const float* src[2]; float* dst[2]; };
__global__ void vtrans_b(VtB vb) {
    __shared__ float t[64][65];
    const int task = blockIdx.z >> 5;
    const int bh = blockIdx.z & 31;
    const float* Yv = vb.src[task];
    float* VT = vb.dst[task];
    const int s0 = blockIdx.x * 64;
    const int b = bh >> 4, h = bh & 15;
    const int tid = threadIdx.x;
    #pragma unroll
    for (int i = 0; i < 16; i++) {
        const int u = i * 256 + tid;
        const int s = u >> 6, d = u & 63;
        t[s][d] = Yv[((size_t)(b * Sn + s0 + s)) * En + h * 64 + d];
    }
    __syncthreads();
    #pragma unroll
    for (int i = 0; i < 16; i++) {
        const int u = i * 256 + tid;
        const int d = u >> 6, s = u & 63;
        VT[((size_t)bh * 64 + d) * Sn + s0 + s] = t[s][d];
    }
}

__global__ void softmax_b(float* __restrict__ wa, float* __restrict__ wb) {
    float* W = blockIdx.y ? wb : wa;
    const int row = blockIdx.x;
    const int q = row & (Sn - 1);
    float* p = W + (size_t)row * Sn;
    const int tid = threadIdx.x;
    const int c0 = tid * 4, c1 = 1024 + tid * 4;
    __shared__ float red[8];

    float4 a = *(float4*)(p + c0);
    float4 b = *(float4*)(p + c1);
    float v[8] = { a.x, a.y, a.z, a.w, b.x, b.y, b.z, b.w };

    float m = -1e30f;
    #pragma unroll
    for (int j = 0; j < 8; j++) {
        const int col = (j < 4) ? (c0 + j) : (c1 + j - 4);
        if (col <= q) m = fmaxf(m, v[j]);
    }
    #pragma unroll
    for (int o = 16; o; o >>= 1) m = fmaxf(m, __shfl_xor_sync(0xffffffffu, m, o));
    if ((tid & 31) == 0) red[tid >> 5] = m;
    __syncthreads();
    if (tid < 32) {
        float mm = (tid < 8) ? red[tid] : -1e30f;
        #pragma unroll
        for (int o = 4; o; o >>= 1) mm = fmaxf(mm, __shfl_xor_sync(0xffffffffu, mm, o));
        if (tid == 0) red[0] = mm;
    }
    __syncthreads();
    m = red[0];
    __syncthreads();

    float sum = 0.f;
    #pragma unroll
    for (int j = 0; j < 8; j++) {
        const int col = (j < 4) ? (c0 + j) : (c1 + j - 4);
        v[j] = (col <= q) ? expf(v[j] - m) : 0.f;
        sum += v[j];
    }
    #pragma unroll
    for (int o = 16; o; o >>= 1) sum += __shfl_xor_sync(0xffffffffu, sum, o);
    if ((tid & 31) == 0) red[tid >> 5] = sum;
    __syncthreads();
    if (tid < 32) {
        float s = (tid < 8) ? red[tid] : 0.f;
        #pragma unroll
        for (int o = 4; o; o >>= 1) s += __shfl_xor_sync(0xffffffffu, s, o);
        if (tid == 0) red[0] = s;
    }
    __syncthreads();
    const float inv = 1.0f / red[0];

    a.x = v[0] * inv; a.y = v[1] * inv; a.z = v[2] * inv; a.w = v[3] * inv;
    b.x = v[4] * inv; b.y = v[5] * inv; b.z = v[6] * inv; b.w = v[7] * inv;
    *(float4*)(p + c0) = a;
    *(float4*)(p + c1) = b;
}

// ============================ launch ============================
extern "C" void kernel_launch(void* const* d_in, const int* in_sizes, int n_in,
                              void* d_out, int out_size) {
    const float* query = (const float*)d_in[0];
    const float* key   = (const float*)d_in[1];
    const float* value = (const float*)d_in[2];
    // d_in[3] = mask (causal tril, hardcoded)
    const float* Wf[7] = {
        (const float*)d_in[4],  (const float*)d_in[5], (const float*)d_in[6],
        (const float*)d_in[7],  (const float*)d_in[8], (const float*)d_in[9],
        (const float*)d_in[10]  // WQ1 WK1 WV1 WQ2 WK2 WV2 WO
    };

    float* out = (float*)d_out;
    float* w1  = out + (size_t)M_ROWS * En;
    float* w2  = w1 + WSZ;

    unsigned char* sc = nullptr;
    cudaGetSymbolAddress((void**)&sc, g_scratch);

    float* Y[6];
    for (int i = 0; i < 6; i++) Y[i] = (float*)(sc + (size_t)(16 * i) * MBb);
    float* QK[4];
    for (int i = 0; i < 4; i++) QK[i] = (float*)(sc + (size_t)(96 + 16 * i) * MBb);
    float* VT[2];
    for (int i = 0; i < 2; i++) VT[i] = (float*)(sc + (size_t)(160 + 16 * i) * MBb);
    float* CC[2];
    for (int i = 0; i < 2; i++) CC[i] = (float*)(sc + (size_t)(192 + 16 * i) * MBb);

    const int SMEM_128 = (2 * 128 + 2 * 128) * 72 * 2 * 2; // 147456
    const int SMEM_64  = (2 * 128 + 2 * 64) * 72 * 2 * 2;  // 110592
    const int SMEM_SC  = (2 * 128 + 4 * 128) * 72 * 2;     // 110592 (A + 2xB bufs)
    cudaFuncSetAttribute((const void*)&gemm2<128, 2, 4, 0, 0>,
                         cudaFuncAttributeMaxDynamicSharedMemorySize, SMEM_128);
    cudaFuncSetAttribute((const void*)&gemm2<128, 2, 4, 0, 1>,
                         cudaFuncAttributeMaxDynamicSharedMemorySize, SMEM_128);
    cudaFuncSetAttribute((const void*)&gemm2<64, 4, 2, 2, 0>,
                         cudaFuncAttributeMaxDynamicSharedMemorySize, SMEM_64);
    cudaFuncSetAttribute((const void*)&scores_nl<4>,
                         cudaFuncAttributeMaxDynamicSharedMemorySize, SMEM_SC);

    // 1) six projections, one launch, BN=128
    PtrBatch bp = {};
    bp.A[0] = query; bp.A[1] = key; bp.A[2] = value;
    bp.A[3] = query; bp.A[4] = key; bp.A[5] = value;
    for (int i = 0; i < 6; i++) { bp.B[i] = Wf[i]; bp.C[i] = Y[i]; }
    gemm2<128, 2, 4, 0, 0><<<dim3(En / 128, M_ROWS / 128, 6), 256, SMEM_128>>>(
        bp, 0, 0, 0, 0, En, En, En, En, 1.f);

    // 2) rope (4 tensors) + V transpose (2 tensors)
    RopeB rb = {};
    rb.src[0] = Y[0]; rb.dst[0] = QK[0];
    rb.src[1] = Y[1]; rb.dst[1] = QK[1];
    rb.src[2] = Y[3]; rb.dst[2] = QK[2];
    rb.src[3] = Y[4]; rb.dst[3] = QK[3];
    rope_b<<<dim3((Bn * Hn * Sn * 32) / 256, 4), 256>>>(rb);
    VtB vb = {};
    vb.src[0] = Y[2]; vb.dst[0] = VT[0];
    vb.src[1] = Y[5]; vb.dst[1] = VT[1];
    vtrans_b<<<dim3(Sn / 64, 1, 64), 256>>>(vb);

    // 3) scores both heads: n-loop kernel, causal sub-tile skip
    PtrBatch bs = {};
    bs.A[0] = QK[0]; bs.B[0] = QK[1]; bs.C[0] = w1;
    bs.A[1] = QK[2]; bs.B[1] = QK[3]; bs.C[1] = w2;
    scores_nl<4><<<dim3(Sn / 512, Sn / 128, 64), 256, SMEM_SC>>>(bs, 0.125f);

    // 4) softmax both heads
    softmax_b<<<dim3(Bn * Hn * Sn, 2), 256>>>(w1, w2);

    // 5) ctx both heads, causal kmax
    PtrBatch bc = {};
    bc.A[0] = w1; bc.B[0] = VT[0]; bc.C[0] = CC[0];
    bc.A[1] = w2; bc.B[1] = VT[1]; bc.C[1] = CC[1];
    gemm2<64, 4, 2, 2, 0><<<dim3(1, Sn / 128, 64), 256, SMEM_64>>>(
        bc, 5, (long long)Sn * Sn, (long long)64 * Sn, (long long)Sn * 64,
        Sn, Sn, 64, Sn, 1.f);

    // 6) output projection with fused ctx1*ctx2 A-load (BK=64 == Dn)
    PtrBatch bo = {};
    bo.A[0] = CC[0]; bo.A2[0] = CC[1]; bo.B[0] = Wf[6]; bo.C[0] = out;
    gemm2<128, 2, 4, 0, 1><<<dim3(En / 128, M_ROWS / 128, 1), 256, SMEM_128>>>(
        bo, 0, 0, 0, 0, En, En, En, En, 1.f);
}

// round 9
// speedup vs baseline: 1.9092x; 1.0093x over previous
#include <cuda_runtime.h>
#include <cuda_fp16.h>
#include <cstdint>
#include <float.h>
#include <math.h>

#define Bn 2
#define Sn 2048
#define Hn 16
#define Dn 64
#define En 1024
#define M_ROWS (Bn*Sn)
#define QSZ ((size_t)Bn*Hn*Sn*Dn)
#define WSZ ((size_t)Bn*Hn*Sn*Sn)
#define MBb (1024ull*1024ull)

// scratch (MB offsets): Y[6]=16i, QK[4]=96+16i, VT[2]=160+16i, CC[2]=192+16i
__device__ __align__(1024) unsigned char g_scratch[224 * 1024 * 1024];

struct PtrBatch {
    const float* A[8];
    const float* A2[8];
    const float* B[8];
    float* C[8];
};

__device__ __forceinline__ uint32_t packh2(float a, float b) {
    __half2 h = __halves2half2(__float2half_rn(a), __float2half_rn(b));
    return *(uint32_t*)&h;
}
__device__ __forceinline__ void ldm_x4(uint32_t* r, uint32_t addr) {
    asm volatile("ldmatrix.sync.aligned.m8n8.x4.shared.b16 {%0,%1,%2,%3}, [%4];"
                 : "=r"(r[0]), "=r"(r[1]), "=r"(r[2]), "=r"(r[3]) : "r"(addr));
}
__device__ __forceinline__ void ldm_x2(uint32_t* r, uint32_t addr) {
    asm volatile("ldmatrix.sync.aligned.m8n8.x2.shared.b16 {%0,%1}, [%2];"
                 : "=r"(r[0]), "=r"(r[1]) : "r"(addr));
}
__device__ __forceinline__ void mma16816(float* d, const uint32_t* a, const uint32_t* b) {
    asm volatile(
        "mma.sync.aligned.m16n8k16.row.col.f32.f16.f16.f32 "
        "{%0,%1,%2,%3}, {%4,%5,%6,%7}, {%8,%9}, {%0,%1,%2,%3};"
        : "+f"(d[0]), "+f"(d[1]), "+f"(d[2]), "+f"(d[3])
        : "r"(a[0]), "r"(a[1]), "r"(a[2]), "r"(a[3]), "r"(b[0]), "r"(b[1]));
}
__device__ __forceinline__ void splitv(const float4 v, uint2& Hi, uint2& Lo) {
    const float hx = __half2float(__float2half_rn(v.x));
    const float hy = __half2float(__float2half_rn(v.y));
    const float hz = __half2float(__float2half_rn(v.z));
    const float hw = __half2float(__float2half_rn(v.w));
    Hi = { packh2(v.x, v.y), packh2(v.z, v.w) };
    Lo = { packh2(v.x - hx, v.y - hy), packh2(v.z - hz, v.w - hw) };
}

// ============================================================================
// Generic f32-in GEMM on fp16 mma.sync: hi/lo split, 3 combos, ldmatrix,
// double-buffered smem. cvt/gload sliced and interleaved between MMA groups.
// C = scale * A @ B^T.  MODE: 0 none, 2 causal kmax.  FUSE: A = A .* A2 (bh xform)
// ============================================================================
template<int BN, int WR, int WCn, int MODE, int FUSE>
__global__ void __launch_bounds__(256) gemm2(
    PtrBatch bt, int zShift,
    long long sAz, long long sBz, long long sCz,
    int lda, int ldb, int ldc, int Kblk, float scale)
{
    constexpr int BM = 128, STR = 72;
    constexpr int THREADS = 256;
    constexpr int WM = BM / WR, WN = BN / WCn;
    constexpr int MF = WM / 16, NF = WN / 8;
    constexpr int ALD = BM * 64 / (4 * THREADS);   // 8
    constexpr int BLD = BN * 64 / (4 * THREADS);   // 8 or 4
    constexpr int BSL = BLD / 4;                   // B elems per slice (2 or 1)
    constexpr int PBUF = (2 * BM + 2 * BN) * STR;

    const int task = blockIdx.z >> zShift;
    const int zb = blockIdx.z & ((1 << zShift) - 1);
    const int m0 = blockIdx.y * BM;
    const int n0 = blockIdx.x * BN;
    const int kmax = (MODE == 2) ? min(Kblk, m0 + BM) : Kblk;
    const int nk = kmax >> 6;

    const float* A = bt.A[task] + (size_t)zb * sAz;
    const float* A2 = FUSE ? bt.A2[task] : nullptr;
    const float* B = bt.B[task] + (size_t)zb * sBz;
    float* C = bt.C[task] + (size_t)zb * sCz;

    extern __shared__ __align__(16) half smh[];

    const int tid = threadIdx.x;
    const int lane = tid & 31;
    const int w = tid >> 5;
    const int wm = (w / WCn) * WM;
    const int wn = (w % WCn) * WN;

    const int g = lane >> 3, r8 = lane & 7;
    const int aRow = r8 + ((g & 1) ? 8 : 0), aCol = (g & 2) ? 8 : 0;
    const uint32_t aOffB = (uint32_t)(((wm + aRow) * STR + aCol) * 2);
    const int bCol = ((lane >> 3) & 1) ? 8 : 0;
    const uint32_t bOffB = (uint32_t)(((wn + r8) * STR + bCol) * 2);

    float acc[MF][NF][4] = {};
    float4 pa[ALD], pb[BLD];

    auto gloadA1 = [&](int kc, int i) {
        const int u = i * THREADS + tid;
        if (FUSE) {
            const int row = m0 + (u >> 4);
            const int b = row >> 11, s = row & (Sn - 1);
            const size_t idx = (((size_t)(b * Hn + kc)) * Sn + s) * 64 + (u & 15) * 4;
            const float4 x = *(const float4*)(A + idx);
            const float4 y = *(const float4*)(A2 + idx);
            pa[i] = { x.x * y.x, x.y * y.y, x.z * y.z, x.w * y.w };
        } else {
            pa[i] = *(const float4*)(A + (size_t)(m0 + (u >> 4)) * lda + kc * 64 + (u & 15) * 4);
        }
    };
    auto gloadB1 = [&](int kc, int i) {
        const int u = i * THREADS + tid;
        pb[i] = *(const float4*)(B + (size_t)(n0 + (u >> 4)) * ldb + kc * 64 + (u & 15) * 4);
    };
    auto cvtA1 = [&](int b, int i) {
        half* Ah = smh + b * PBUF;
        half* Al = Ah + BM * STR;
        const int u = i * THREADS + tid;
        uint2 Hi, Lo;
        splitv(pa[i], Hi, Lo);
        *(uint2*)&Ah[(u >> 4) * STR + (u & 15) * 4] = Hi;
        *(uint2*)&Al[(u >> 4) * STR + (u & 15) * 4] = Lo;
    };
    auto cvtB1 = [&](int b, int i) {
        half* Bh = smh + b * PBUF + 2 * BM * STR;
        half* Bl = Bh + BN * STR;
        const int u = i * THREADS + tid;
        uint2 Hi, Lo;
        splitv(pb[i], Hi, Lo);
        *(uint2*)&Bh[(u >> 4) * STR + (u & 15) * 4] = Hi;
        *(uint2*)&Bl[(u >> 4) * STR + (u & 15) * 4] = Lo;
    };

    // prolog
    #pragma unroll
    for (int i = 0; i < ALD; i++) gloadA1(0, i);
    #pragma unroll
    for (int i = 0; i < BLD; i++) gloadB1(0, i);
    #pragma unroll
    for (int i = 0; i < ALD; i++) cvtA1(0, i);
    #pragma unroll
    for (int i = 0; i < BLD; i++) cvtB1(0, i);
    if (nk > 1) {
        #pragma unroll
        for (int i = 0; i < ALD; i++) gloadA1(1, i);
        #pragma unroll
        for (int i = 0; i < BLD; i++) gloadB1(1, i);
    }

    for (int kc = 0; kc < nk; kc++) {
        __syncthreads();
        const int b = kc & 1;
        const uint32_t AhB = (uint32_t)__cvta_generic_to_shared(smh + b * PBUF);
        const uint32_t AlB = AhB + BM * STR * 2;
        const uint32_t BhB = AlB + BM * STR * 2;
        const uint32_t BlB = BhB + BN * STR * 2;
        const bool hasCvt = (kc + 1 < nk);
        const bool hasLd = (kc + 2 < nk);

        #pragma unroll
        for (int ks = 0; ks < 4; ks++) {
            uint32_t ah[MF][4], al[MF][4], bh[NF][2], bl[NF][2];
            #pragma unroll
            for (int mf = 0; mf < MF; mf++) {
                const uint32_t off = aOffB + (uint32_t)((mf * 16 * STR + ks * 16) * 2);
                ldm_x4(ah[mf], AhB + off);
                ldm_x4(al[mf], AlB + off);
            }
            #pragma unroll
            for (int nf = 0; nf < NF; nf++) {
                const uint32_t off = bOffB + (uint32_t)((nf * 8 * STR + ks * 16) * 2);
                ldm_x2(bh[nf], BhB + off);
                ldm_x2(bl[nf], BlB + off);
            }
            #pragma unroll
            for (int mf = 0; mf < MF; mf++)
                #pragma unroll
                for (int nf = 0; nf < NF; nf++)
                    mma16816(acc[mf][nf], ah[mf], bh[nf]);
            // cvt slice of next buffer between MMA groups
            if (hasCvt) {
                const int nb = (kc + 1) & 1;
                cvtA1(nb, 2 * ks);
                cvtA1(nb, 2 * ks + 1);
                #pragma unroll
                for (int q = 0; q < BSL; q++) cvtB1(nb, BSL * ks + q);
            }
            #pragma unroll
            for (int mf = 0; mf < MF; mf++)
                #pragma unroll
                for (int nf = 0; nf < NF; nf++)
                    mma16816(acc[mf][nf], ah[mf], bl[nf]);
            // global prefetch slice for chunk kc+2 (refills slots just consumed)
            if (hasLd) {
                gloadA1(kc + 2, 2 * ks);
                gloadA1(kc + 2, 2 * ks + 1);
                #pragma unroll
                for (int q = 0; q < BSL; q++) gloadB1(kc + 2, BSL * ks + q);
            }
            #pragma unroll
            for (int mf = 0; mf < MF; mf++)
                #pragma unroll
                for (int nf = 0; nf < NF; nf++)
                    mma16816(acc[mf][nf], al[mf], bh[nf]);
        }
    }

    #pragma unroll
    for (int mf = 0; mf < MF; mf++) {
        const int row = m0 + wm + mf * 16 + (lane >> 2);
        #pragma unroll
        for (int nf = 0; nf < NF; nf++) {
            const int col = n0 + wn + nf * 8 + (lane & 3) * 2;
            float2 v0 = { acc[mf][nf][0] * scale, acc[mf][nf][1] * scale };
            float2 v1 = { acc[mf][nf][2] * scale, acc[mf][nf][3] * scale };
            *(float2*)&C[(size_t)row * ldc + col] = v0;
            *(float2*)&C[(size_t)(row + 8) * ldc + col] = v1;
        }
    }
}

// ============================================================================
// Scores: K=64 (one chunk). Q tile resident; sweep NSUB 128-col k-subtiles,
// B double-buffered, gload slices interleaved between MMA groups. Causal skip.
// ============================================================================
template<int NSUB>
__global__ void __launch_bounds__(256) scores_nl(PtrBatch bt, float scale)
{
    constexpr int BM = 128, BNS = 128, STR = 72;
    constexpr int THREADS = 256;
    constexpr int WCn = 4;
    constexpr int WM = 64, WN = 32;
    constexpr int MF = 4, NF = 4;
    constexpr int ALD = 8, BLD = 8;

    const int task = blockIdx.z >> 5;
    const int bh = blockIdx.z & 31;
    const int m0 = blockIdx.y * BM;
    const int nbase = blockIdx.x * BNS * NSUB;
    if (nbase > m0 + BM - 1) return;
    const int nActive = min(NSUB, (m0 + BM - 1 - nbase) / BNS + 1);

    const float* A = bt.A[task] + (size_t)bh * Sn * 64;
    const float* B = bt.B[task] + (size_t)bh * Sn * 64;
    float* C = bt.C[task] + (size_t)bh * Sn * Sn;

    extern __shared__ __align__(16) half smh[];
    half* Ah = smh;
    half* Al = Ah + BM * STR;
    half* Bbuf = Al + BM * STR;
    constexpr int BBUF = 2 * BNS * STR;

    const int tid = threadIdx.x;
    const int lane = tid & 31;
    const int w = tid >> 5;
    const int wm = (w / WCn) * WM;
    const int wn = (w % WCn) * WN;

    const int g = lane >> 3, r8 = lane & 7;
    const int aRow = r8 + ((g & 1) ? 8 : 0), aCol = (g & 2) ? 8 : 0;
    const uint32_t aOffB = (uint32_t)(((wm + aRow) * STR + aCol) * 2);
    const int bCol = ((lane >> 3) & 1) ? 8 : 0;
    const uint32_t bOffB = (uint32_t)(((wn + r8) * STR + bCol) * 2);

    float4 pa[ALD], pb[BLD];

    #pragma unroll
    for (int i = 0; i < ALD; i++) {
        const int u = i * THREADS + tid;
        pa[i] = *(const float4*)(A + (size_t)(m0 + (u >> 4)) * 64 + (u & 15) * 4);
    }
    #pragma unroll
    for (int i = 0; i < ALD; i++) {
        const int u = i * THREADS + tid;
        uint2 Hi, Lo;
        splitv(pa[i], Hi, Lo);
        *(uint2*)&Ah[(u >> 4) * STR + (u & 15) * 4] = Hi;
        *(uint2*)&Al[(u >> 4) * STR + (u & 15) * 4] = Lo;
    }

    auto gloadB1 = [&](int nn, int i) {
        const int n0 = nbase + nn * BNS;
        const int u = i * THREADS + tid;
        pb[i] = *(const float4*)(B + (size_t)(n0 + (u >> 4)) * 64 + (u & 15) * 4);
    };
    auto cvtB = [&](int buf) {
        half* Bh = Bbuf + buf * BBUF;
        half* Bl = Bh + BNS * STR;
        #pragma unroll
        for (int i = 0; i < BLD; i++) {
            const int u = i * THREADS + tid;
            uint2 Hi, Lo;
            splitv(pb[i], Hi, Lo);
            *(uint2*)&Bh[(u >> 4) * STR + (u & 15) * 4] = Hi;
            *(uint2*)&Bl[(u >> 4) * STR + (u & 15) * 4] = Lo;
        }
    };

    #pragma unroll
    for (int i = 0; i < BLD; i++) gloadB1(0, i);
    cvtB(0);
    __syncthreads();

    const uint32_t AhB = (uint32_t)__cvta_generic_to_shared(Ah);
    const uint32_t AlB = AhB + BM * STR * 2;

    for (int nn = 0; nn < nActive; nn++) {
        const bool hasNext = (nn + 1 < nActive);
        const uint32_t BhB = (uint32_t)__cvta_generic_to_shared(Bbuf + (nn & 1) * BBUF);
        const uint32_t BlB = BhB + BNS * STR * 2;

        float acc[MF][NF][4] = {};
        #pragma unroll
        for (int ks = 0; ks < 4; ks++) {
            uint32_t ah[MF][4], al[MF][4], bh[NF][2], bl[NF][2];
            #pragma unroll
            for (int mf = 0; mf < MF; mf++) {
                const uint32_t off = aOffB + (uint32_t)((mf * 16 * STR + ks * 16) * 2);
                ldm_x4(ah[mf], AhB + off);
                ldm_x4(al[mf], AlB + off);
            }
            #pragma unroll
            for (int nf = 0; nf < NF; nf++) {
                const uint32_t off = bOffB + (uint32_t)((nf * 8 * STR + ks * 16) * 2);
                ldm_x2(bh[nf], BhB + off);
                ldm_x2(bl[nf], BlB + off);
            }
            #pragma unroll
            for (int mf = 0; mf < MF; mf++)
                #pragma unroll
                for (int nf = 0; nf < NF; nf++)
                    mma16816(acc[mf][nf], ah[mf], bh[nf]);
            if (hasNext) {
                gloadB1(nn + 1, 2 * ks);
                gloadB1(nn + 1, 2 * ks + 1);
            }
            #pragma unroll
            for (int mf = 0; mf < MF; mf++)
                #pragma unroll
                for (int nf = 0; nf < NF; nf++)
                    mma16816(acc[mf][nf], ah[mf], bl[nf]);
            #pragma unroll
            for (int mf = 0; mf < MF; mf++)
                #pragma unroll
                for (int nf = 0; nf < NF; nf++)
                    mma16816(acc[mf][nf], al[mf], bh[nf]);
        }

        const int n0 = nbase + nn * BNS;
        #pragma unroll
        for (int mf = 0; mf < MF; mf++) {
            const int row = m0 + wm + mf * 16 + (lane >> 2);
            #pragma unroll
            for (int nf = 0; nf < NF; nf++) {
                const int col = n0 + wn + nf * 8 + (lane & 3) * 2;
                float2 v0 = { acc[mf][nf][0] * scale, acc[mf][nf][1] * scale };
                float2 v1 = { acc[mf][nf][2] * scale, acc[mf][nf][3] * scale };
                *(float2*)&C[(size_t)row * Sn + col] = v0;
                *(float2*)&C[(size_t)(row + 8) * Sn + col] = v1;
            }
        }

        if (hasNext) {
            cvtB((nn + 1) & 1);
            __syncthreads();
        }
    }
}

// ============================ aux kernels ============================
struct RopeB { const float* src[4]; float* dst[4]; };
__global__ void rope_b(RopeB rb) {
    const int i = blockIdx.x * 256 + threadIdx.x;
    const float* Y = rb.src[blockIdx.y];
    float* Qr = rb.dst[blockIdx.y];
    const int j = i & 31;
    const int s = (i >> 5) & (Sn - 1);
    const int bh = i >> 16;
    const int b = bh >> 4, h = bh & 15;
    const float* yr = Y + ((size_t)(b * Sn + s)) * En + h * 64;
    const float x1 = yr[j], x2 = yr[j + 32];
    const double invf = pow(10000.0, -(double)j / 32.0);
    const float ang = (float)((double)s * invf);
    const float sv = sinf(ang), cv = cosf(ang);
    float* o = Qr + ((size_t)bh * Sn + s) * 64;
    o[j]      = x1 * cv - x2 * sv;
    o[j + 32] = x1 * sv + x2 * cv;
}

struct VtB { const float* src[2]; float* dst[2]; };
__global__ void vtrans_b(VtB vb) {
    __shared__ float t[64][65];
    const int task = blockIdx.z >> 5;
    const int bh = blockIdx.z & 31;
    const float* Yv = vb.src[task];
    float* VT = vb.dst[task];
    const int s0 = blockIdx.x * 64;
    const int b = bh >> 4, h = bh & 15;
    const int tid = threadIdx.x;
    #pragma unroll
    for (int i = 0; i < 16; i++) {
        const int u = i * 256 + tid;
        const int s = u >> 6, d = u & 63;
        t[s][d] = Yv[((size_t)(b * Sn + s0 + s)) * En + h * 64 + d];
    }
    __syncthreads();
    #pragma unroll
    for (int i = 0; i < 16; i++) {
        const int u = i * 256 + tid;
        const int d = u >> 6, s = u & 63;
        VT[((size_t)bh * 64 + d) * Sn + s0 + s] = t[s][d];
    }
}

// causal softmax in place; loads only chunks intersecting the valid prefix
__global__ void softmax_b(float* __restrict__ wa, float* __restrict__ wb) {
    float* W = blockIdx.y ? wb : wa;
    const int row = blockIdx.x;
    const int q = row & (Sn - 1);
    float* p = W + (size_t)row * Sn;
    const int tid = threadIdx.x;
    const int c0 = tid * 4, c1 = 1024 + tid * 4;
    __shared__ float red[8];

    const float4 z4 = { 0.f, 0.f, 0.f, 0.f };
    float4 a = (c0 <= q) ? *(float4*)(p + c0) : z4;
    float4 b = (c1 <= q) ? *(float4*)(p + c1) : z4;
    float v[8] = { a.x, a.y, a.z, a.w, b.x, b.y, b.z, b.w };

    float m = -1e30f;
    #pragma unroll
    for (int j = 0; j < 8; j++) {
        const int col = (j < 4) ? (c0 + j) : (c1 + j - 4);
        if (col <= q) m = fmaxf(m, v[j]);
    }
    #pragma unroll
    for (int o = 16; o; o >>= 1) m = fmaxf(m, __shfl_xor_sync(0xffffffffu, m, o));
    if ((tid & 31) == 0) red[tid >> 5] = m;
    __syncthreads();
    if (tid < 32) {
        float mm = (tid < 8) ? red[tid] : -1e30f;
        #pragma unroll
        for (int o = 4; o; o >>= 1) mm = fmaxf(mm, __shfl_xor_sync(0xffffffffu, mm, o));
        if (tid == 0) red[0] = mm;
    }
    __syncthreads();
    m = red[0];
    __syncthreads();

    float sum = 0.f;
    #pragma unroll
    for (int j = 0; j < 8; j++) {
        const int col = (j < 4) ? (c0 + j) : (c1 + j - 4);
        v[j] = (col <= q) ? expf(v[j] - m) : 0.f;
        sum += v[j];
    }
    #pragma unroll
    for (int o = 16; o; o >>= 1) sum += __shfl_xor_sync(0xffffffffu, sum, o);
    if ((tid & 31) == 0) red[tid >> 5] = sum;
    __syncthreads();
    if (tid < 32) {
        float s = (tid < 8) ? red[tid] : 0.f;
        #pragma unroll
        for (int o = 4; o; o >>= 1) s += __shfl_xor_sync(0xffffffffu, s, o);
        if (tid == 0) red[0] = s;
    }
    __syncthreads();
    const float inv = 1.0f / red[0];

    a.x = v[0] * inv; a.y = v[1] * inv; a.z = v[2] * inv; a.w = v[3] * inv;
    b.x = v[4] * inv; b.y = v[5] * inv; b.z = v[6] * inv; b.w = v[7] * inv;
    *(float4*)(p + c0) = a;
    *(float4*)(p + c1) = b;
}

// ============================ launch ============================
extern "C" void kernel_launch(void* const* d_in, const int* in_sizes, int n_in,
                              void* d_out, int out_size) {
    const float* query = (const float*)d_in[0];
    const float* key   = (const float*)d_in[1];
    const float* value = (const float*)d_in[2];
    // d_in[3] = mask (causal tril, hardcoded)
    const float* Wf[7] = {
        (const float*)d_in[4],  (const float*)d_in[5], (const float*)d_in[6],
        (const float*)d_in[7],  (const float*)d_in[8], (const float*)d_in[9],
        (const float*)d_in[10]
    };

    float* out = (float*)d_out;
    float* w1  = out + (size_t)M_ROWS * En;
    float* w2  = w1 + WSZ;

    unsigned char* sc = nullptr;
    cudaGetSymbolAddress((void**)&sc, g_scratch);

    float* Y[6];
    for (int i = 0; i < 6; i++) Y[i] = (float*)(sc + (size_t)(16 * i) * MBb);
    float* QK[4];
    for (int i = 0; i < 4; i++) QK[i] = (float*)(sc + (size_t)(96 + 16 * i) * MBb);
    float* VT[2];
    for (int i = 0; i < 2; i++) VT[i] = (float*)(sc + (size_t)(160 + 16 * i) * MBb);
    float* CC[2];
    for (int i = 0; i < 2; i++) CC[i] = (float*)(sc + (size_t)(192 + 16 * i) * MBb);

    const int SMEM_128 = (2 * 128 + 2 * 128) * 72 * 2 * 2; // 147456
    const int SMEM_64  = (2 * 128 + 2 * 64) * 72 * 2 * 2;  // 110592
    const int SMEM_SC  = (2 * 128 + 4 * 128) * 72 * 2;     // 110592
    cudaFuncSetAttribute((const void*)&gemm2<128, 2, 4, 0, 0>,
                         cudaFuncAttributeMaxDynamicSharedMemorySize, SMEM_128);
    cudaFuncSetAttribute((const void*)&gemm2<128, 2, 4, 0, 1>,
                         cudaFuncAttributeMaxDynamicSharedMemorySize, SMEM_128);
    cudaFuncSetAttribute((const void*)&gemm2<64, 4, 2, 2, 0>,
                         cudaFuncAttributeMaxDynamicSharedMemorySize, SMEM_64);
    cudaFuncSetAttribute((const void*)&scores_nl<8>,
                         cudaFuncAttributeMaxDynamicSharedMemorySize, SMEM_SC);

    // 1) six projections, one launch, BN=128
    PtrBatch bp = {};
    bp.A[0] = query; bp.A[1] = key; bp.A[2] = value;
    bp.A[3] = query; bp.A[4] = key; bp.A[5] = value;
    for (int i = 0; i < 6; i++) { bp.B[i] = Wf[i]; bp.C[i] = Y[i]; }
    gemm2<128, 2, 4, 0, 0><<<dim3(En / 128, M_ROWS / 128, 6), 256, SMEM_128>>>(
        bp, 0, 0, 0, 0, En, En, En, En, 1.f);

    // 2) rope (4 tensors) + V transpose (2 tensors)
    RopeB rb = {};
    rb.src[0] = Y[0]; rb.dst[0] = QK[0];
    rb.src[1] = Y[1]; rb.dst[1] = QK[1];
    rb.src[2] = Y[3]; rb.dst[2] = QK[2];
    rb.src[3] = Y[4]; rb.dst[3] = QK[3];
    rope_b<<<dim3((Bn * Hn * Sn * 32) / 256, 4), 256>>>(rb);
    VtB vb = {};
    vb.src[0] = Y[2]; vb.dst[0] = VT[0];
    vb.src[1] = Y[5]; vb.dst[1] = VT[1];
    vtrans_b<<<dim3(Sn / 64, 1, 64), 256>>>(vb);

    // 3) scores both heads: NSUB=8 n-loop, causal skip
    PtrBatch bs = {};
    bs.A[0] = QK[0]; bs.B[0] = QK[1]; bs.C[0] = w1;
    bs.A[1] = QK[2]; bs.B[1] = QK[3]; bs.C[1] = w2;
    scores_nl<8><<<dim3(Sn / 1024, Sn / 128, 64), 256, SMEM_SC>>>(bs, 0.125f);

    // 4) softmax both heads (prefix loads)
    softmax_b<<<dim3(Bn * Hn * Sn, 2), 256>>>(w1, w2);

    // 5) ctx both heads, causal kmax
    PtrBatch bc = {};
    bc.A[0] = w1; bc.B[0] = VT[0]; bc.C[0] = CC[0];
    bc.A[1] = w2; bc.B[1] = VT[1]; bc.C[1] = CC[1];
    gemm2<64, 4, 2, 2, 0><<<dim3(1, Sn / 128, 64), 256, SMEM_64>>>(
        bc, 5, (long long)Sn * Sn, (long long)64 * Sn, (long long)Sn * 64,
        Sn, Sn, 64, Sn, 1.f);

    // 6) output projection with fused ctx1*ctx2 A-load
    PtrBatch bo = {};
    bo.A[0] = CC[0]; bo.A2[0] = CC[1]; bo.B[0] = Wf[6]; bo.C[0] = out;
    gemm2<128, 2, 4, 0, 1><<<dim3(En / 128, M_ROWS / 128, 1), 256, SMEM_128>>>(
        bo, 0, 0, 0, 0, En, En, En, En, 1.f);
}

// round 10
// speedup vs baseline: 1.9160x; 1.0036x over previous
#include <cuda_runtime.h>
#include <cuda_fp16.h>
#include <cstdint>
#include <float.h>
#include <math.h>

#define Bn 2
#define Sn 2048
#define Hn 16
#define Dn 64
#define En 1024
#define M_ROWS (Bn*Sn)
#define QSZ ((size_t)Bn*Hn*Sn*Dn)
#define WSZ ((size_t)Bn*Hn*Sn*Sn)
#define MBb (1024ull*1024ull)

// scratch (MB offsets): Y[6]=16i, QK[4]=96+16i, VT[2]=160+16i, CC[2]=192+16i
__device__ __align__(1024) unsigned char g_scratch[224 * 1024 * 1024];

struct PtrBatch {
    const float* A[8];
    const float* A2[8];
    const float* B[8];
    float* C[8];
};

__device__ __forceinline__ uint32_t packh2(float a, float b) {
    __half2 h = __halves2half2(__float2half_rn(a), __float2half_rn(b));
    return *(uint32_t*)&h;
}
__device__ __forceinline__ void ldm_x4(uint32_t* r, uint32_t addr) {
    asm volatile("ldmatrix.sync.aligned.m8n8.x4.shared.b16 {%0,%1,%2,%3}, [%4];"
                 : "=r"(r[0]), "=r"(r[1]), "=r"(r[2]), "=r"(r[3]) : "r"(addr));
}
__device__ __forceinline__ void mma16816(float* d, const uint32_t* a, const uint32_t* b) {
    asm volatile(
        "mma.sync.aligned.m16n8k16.row.col.f32.f16.f16.f32 "
        "{%0,%1,%2,%3}, {%4,%5,%6,%7}, {%8,%9}, {%0,%1,%2,%3};"
        : "+f"(d[0]), "+f"(d[1]), "+f"(d[2]), "+f"(d[3])
        : "r"(a[0]), "r"(a[1]), "r"(a[2]), "r"(a[3]), "r"(b[0]), "r"(b[1]));
}
__device__ __forceinline__ void splitv(const float4 v, uint2& Hi, uint2& Lo) {
    const float hx = __half2float(__float2half_rn(v.x));
    const float hy = __half2float(__float2half_rn(v.y));
    const float hz = __half2float(__float2half_rn(v.z));
    const float hw = __half2float(__float2half_rn(v.w));
    Hi = { packh2(v.x, v.y), packh2(v.z, v.w) };
    Lo = { packh2(v.x - hx, v.y - hy), packh2(v.z - hz, v.w - hw) };
}

// ============================================================================
// 512-thread (16 warp) f32-in GEMM on fp16 mma.sync: hi/lo split, 3 combos,
// ldmatrix x4 for A and B-pairs, double-buffered smem, sliced cvt/prefetch.
// Warp tile 32 x 32 (BN=128) or 32 x 16 (BN=64).  C = scale * A @ B^T.
// MODE: 0 none, 2 causal kmax.  FUSE: A = A .* A2 with bh index transform.
// ============================================================================
template<int BN, int MODE, int FUSE>
__global__ void __launch_bounds__(512) gemm2(
    PtrBatch bt, int zShift,
    long long sAz, long long sBz, long long sCz,
    int lda, int ldb, int ldc, int Kblk, float scale)
{
    constexpr int BM = 128, STR = 72;
    constexpr int THREADS = 512;
    constexpr int WCn = 4;
    constexpr int WM = 32, WN = BN / WCn;          // 32 or 16
    constexpr int MF = 2, NF = WN / 8;             // 4 or 2
    constexpr int NFP = NF / 2;                    // 2 or 1
    constexpr int ALD = BM * 64 / (4 * THREADS);   // 4
    constexpr int BLD = BN * 64 / (4 * THREADS);   // 4 or 2
    constexpr int PBUF = (2 * BM + 2 * BN) * STR;

    const int task = blockIdx.z >> zShift;
    const int zb = blockIdx.z & ((1 << zShift) - 1);
    const int m0 = blockIdx.y * BM;
    const int n0 = blockIdx.x * BN;
    const int kmax = (MODE == 2) ? min(Kblk, m0 + BM) : Kblk;
    const int nk = kmax >> 6;

    const float* A = bt.A[task] + (size_t)zb * sAz;
    const float* A2 = FUSE ? bt.A2[task] : nullptr;
    const float* B = bt.B[task] + (size_t)zb * sBz;
    float* C = bt.C[task] + (size_t)zb * sCz;

    extern __shared__ __align__(16) half smh[];

    const int tid = threadIdx.x;
    const int lane = tid & 31;
    const int w = tid >> 5;
    const int wm = (w / WCn) * WM;
    const int wn = (w % WCn) * WN;

    const int r8 = lane & 7;
    const int g = lane >> 3;
    // A x4: rows r8 + (g&1)*8, col (g&2)*4 halves
    const uint32_t aOffB = (uint32_t)(((wm + r8 + (g & 1) * 8) * STR + ((g >> 1) * 8)) * 2);
    // B x4 (n-pair): rows r8 + ((lane>>4)&1)*8, col ((lane>>3)&1)*8
    const uint32_t bOffB = (uint32_t)(((wn + r8 + ((lane >> 4) & 1) * 8) * STR + (((lane >> 3) & 1) * 8)) * 2);

    float acc[MF][NF][4] = {};
    float4 pa[ALD], pb[BLD];

    auto gloadA1 = [&](int kc, int i) {
        const int u = i * THREADS + tid;
        if (FUSE) {
            const int row = m0 + (u >> 4);
            const int b = row >> 11, s = row & (Sn - 1);
            const size_t idx = (((size_t)(b * Hn + kc)) * Sn + s) * 64 + (u & 15) * 4;
            const float4 x = *(const float4*)(A + idx);
            const float4 y = *(const float4*)(A2 + idx);
            pa[i] = { x.x * y.x, x.y * y.y, x.z * y.z, x.w * y.w };
        } else {
            pa[i] = *(const float4*)(A + (size_t)(m0 + (u >> 4)) * lda + kc * 64 + (u & 15) * 4);
        }
    };
    auto gloadB1 = [&](int kc, int i) {
        const int u = i * THREADS + tid;
        pb[i] = *(const float4*)(B + (size_t)(n0 + (u >> 4)) * ldb + kc * 64 + (u & 15) * 4);
    };
    auto cvtA1 = [&](int b, int i) {
        half* Ah = smh + b * PBUF;
        half* Al = Ah + BM * STR;
        const int u = i * THREADS + tid;
        uint2 Hi, Lo;
        splitv(pa[i], Hi, Lo);
        *(uint2*)&Ah[(u >> 4) * STR + (u & 15) * 4] = Hi;
        *(uint2*)&Al[(u >> 4) * STR + (u & 15) * 4] = Lo;
    };
    auto cvtB1 = [&](int b, int i) {
        half* Bh = smh + b * PBUF + 2 * BM * STR;
        half* Bl = Bh + BN * STR;
        const int u = i * THREADS + tid;
        uint2 Hi, Lo;
        splitv(pb[i], Hi, Lo);
        *(uint2*)&Bh[(u >> 4) * STR + (u & 15) * 4] = Hi;
        *(uint2*)&Bl[(u >> 4) * STR + (u & 15) * 4] = Lo;
    };

    #pragma unroll
    for (int i = 0; i < ALD; i++) gloadA1(0, i);
    #pragma unroll
    for (int i = 0; i < BLD; i++) gloadB1(0, i);
    #pragma unroll
    for (int i = 0; i < ALD; i++) cvtA1(0, i);
    #pragma unroll
    for (int i = 0; i < BLD; i++) cvtB1(0, i);
    if (nk > 1) {
        #pragma unroll
        for (int i = 0; i < ALD; i++) gloadA1(1, i);
        #pragma unroll
        for (int i = 0; i < BLD; i++) gloadB1(1, i);
    }

    for (int kc = 0; kc < nk; kc++) {
        __syncthreads();
        const int b = kc & 1;
        const uint32_t AhB = (uint32_t)__cvta_generic_to_shared(smh + b * PBUF);
        const uint32_t AlB = AhB + BM * STR * 2;
        const uint32_t BhB = AlB + BM * STR * 2;
        const uint32_t BlB = BhB + BN * STR * 2;
        const bool hasCvt = (kc + 1 < nk);
        const bool hasLd = (kc + 2 < nk);
        const int nb = (kc + 1) & 1;

        #pragma unroll
        for (int ks = 0; ks < 4; ks++) {
            uint32_t ah[MF][4], al[MF][4];
            #pragma unroll
            for (int mf = 0; mf < MF; mf++) {
                const uint32_t off = aOffB + (uint32_t)((mf * 16 * STR + ks * 16) * 2);
                ldm_x4(ah[mf], AhB + off);
                ldm_x4(al[mf], AlB + off);
            }
            // cvt slice of next chunk between fragment load and MMA
            if (hasCvt) {
                cvtA1(nb, ks);
                if (ks < BLD) cvtB1(nb, ks);
            }
            #pragma unroll
            for (int nfp = 0; nfp < NFP; nfp++) {
                uint32_t bh2[4], bl2[4];
                const uint32_t off = bOffB + (uint32_t)((nfp * 16 * STR + ks * 16) * 2);
                ldm_x4(bh2, BhB + off);
                ldm_x4(bl2, BlB + off);
                #pragma unroll
                for (int mf = 0; mf < MF; mf++) {
                    mma16816(acc[mf][2 * nfp],     ah[mf], bh2);
                    mma16816(acc[mf][2 * nfp + 1], ah[mf], bh2 + 2);
                    mma16816(acc[mf][2 * nfp],     al[mf], bh2);
                    mma16816(acc[mf][2 * nfp + 1], al[mf], bh2 + 2);
                    mma16816(acc[mf][2 * nfp],     ah[mf], bl2);
                    mma16816(acc[mf][2 * nfp + 1], ah[mf], bl2 + 2);
                }
            }
            // global prefetch slice for chunk kc+2
            if (hasLd) {
                gloadA1(kc + 2, ks);
                if (ks < BLD) gloadB1(kc + 2, ks);
            }
        }
    }

    #pragma unroll
    for (int mf = 0; mf < MF; mf++) {
        const int row = m0 + wm + mf * 16 + (lane >> 2);
        #pragma unroll
        for (int nf = 0; nf < NF; nf++) {
            const int col = n0 + wn + nf * 8 + (lane & 3) * 2;
            float2 v0 = { acc[mf][nf][0] * scale, acc[mf][nf][1] * scale };
            float2 v1 = { acc[mf][nf][2] * scale, acc[mf][nf][3] * scale };
            *(float2*)&C[(size_t)row * ldc + col] = v0;
            *(float2*)&C[(size_t)(row + 8) * ldc + col] = v1;
        }
    }
}

// ============================================================================
// Scores: 512 threads, K=64 one chunk, Q resident, NSUB 128-col k-subtiles,
// B double-buffered, gload interleaved. Causal subtile skip.
// ============================================================================
template<int NSUB>
__global__ void __launch_bounds__(512) scores_nl(PtrBatch bt, float scale)
{
    constexpr int BM = 128, BNS = 128, STR = 72;
    constexpr int THREADS = 512;
    constexpr int WCn = 4;
    constexpr int WM = 32, WN = 32;
    constexpr int MF = 2, NF = 4, NFP = 2;
    constexpr int ALD = 4, BLD = 4;

    const int task = blockIdx.z >> 5;
    const int bh = blockIdx.z & 31;
    const int m0 = blockIdx.y * BM;
    const int nbase = blockIdx.x * BNS * NSUB;
    if (nbase > m0 + BM - 1) return;
    const int nActive = min(NSUB, (m0 + BM - 1 - nbase) / BNS + 1);

    const float* A = bt.A[task] + (size_t)bh * Sn * 64;
    const float* B = bt.B[task] + (size_t)bh * Sn * 64;
    float* C = bt.C[task] + (size_t)bh * Sn * Sn;

    extern __shared__ __align__(16) half smh[];
    half* Ah = smh;
    half* Al = Ah + BM * STR;
    half* Bbuf = Al + BM * STR;
    constexpr int BBUF = 2 * BNS * STR;

    const int tid = threadIdx.x;
    const int lane = tid & 31;
    const int w = tid >> 5;
    const int wm = (w / WCn) * WM;
    const int wn = (w % WCn) * WN;

    const int r8 = lane & 7;
    const int g = lane >> 3;
    const uint32_t aOffB = (uint32_t)(((wm + r8 + (g & 1) * 8) * STR + ((g >> 1) * 8)) * 2);
    const uint32_t bOffB = (uint32_t)(((wn + r8 + ((lane >> 4) & 1) * 8) * STR + (((lane >> 3) & 1) * 8)) * 2);

    float4 pa[ALD], pb[BLD];

    #pragma unroll
    for (int i = 0; i < ALD; i++) {
        const int u = i * THREADS + tid;
        pa[i] = *(const float4*)(A + (size_t)(m0 + (u >> 4)) * 64 + (u & 15) * 4);
    }
    #pragma unroll
    for (int i = 0; i < ALD; i++) {
        const int u = i * THREADS + tid;
        uint2 Hi, Lo;
        splitv(pa[i], Hi, Lo);
        *(uint2*)&Ah[(u >> 4) * STR + (u & 15) * 4] = Hi;
        *(uint2*)&Al[(u >> 4) * STR + (u & 15) * 4] = Lo;
    }

    auto gloadB1 = [&](int nn, int i) {
        const int n0 = nbase + nn * BNS;
        const int u = i * THREADS + tid;
        pb[i] = *(const float4*)(B + (size_t)(n0 + (u >> 4)) * 64 + (u & 15) * 4);
    };
    auto cvtB = [&](int buf) {
        half* Bh = Bbuf + buf * BBUF;
        half* Bl = Bh + BNS * STR;
        #pragma unroll
        for (int i = 0; i < BLD; i++) {
            const int u = i * THREADS + tid;
            uint2 Hi, Lo;
            splitv(pb[i], Hi, Lo);
            *(uint2*)&Bh[(u >> 4) * STR + (u & 15) * 4] = Hi;
            *(uint2*)&Bl[(u >> 4) * STR + (u & 15) * 4] = Lo;
        }
    };

    #pragma unroll
    for (int i = 0; i < BLD; i++) gloadB1(0, i);
    cvtB(0);
    __syncthreads();

    const uint32_t AhB = (uint32_t)__cvta_generic_to_shared(Ah);
    const uint32_t AlB = AhB + BM * STR * 2;

    for (int nn = 0; nn < nActive; nn++) {
        const bool hasNext = (nn + 1 < nActive);
        const uint32_t BhB = (uint32_t)__cvta_generic_to_shared(Bbuf + (nn & 1) * BBUF);
        const uint32_t BlB = BhB + BNS * STR * 2;

        float acc[MF][NF][4] = {};
        #pragma unroll
        for (int ks = 0; ks < 4; ks++) {
            uint32_t ah[MF][4], al[MF][4];
            #pragma unroll
            for (int mf = 0; mf < MF; mf++) {
                const uint32_t off = aOffB + (uint32_t)((mf * 16 * STR + ks * 16) * 2);
                ldm_x4(ah[mf], AhB + off);
                ldm_x4(al[mf], AlB + off);
            }
            if (hasNext) gloadB1(nn + 1, ks);
            #pragma unroll
            for (int nfp = 0; nfp < NFP; nfp++) {
                uint32_t bh2[4], bl2[4];
                const uint32_t off = bOffB + (uint32_t)((nfp * 16 * STR + ks * 16) * 2);
                ldm_x4(bh2, BhB + off);
                ldm_x4(bl2, BlB + off);
                #pragma unroll
                for (int mf = 0; mf < MF; mf++) {
                    mma16816(acc[mf][2 * nfp],     ah[mf], bh2);
                    mma16816(acc[mf][2 * nfp + 1], ah[mf], bh2 + 2);
                    mma16816(acc[mf][2 * nfp],     al[mf], bh2);
                    mma16816(acc[mf][2 * nfp + 1], al[mf], bh2 + 2);
                    mma16816(acc[mf][2 * nfp],     ah[mf], bl2);
                    mma16816(acc[mf][2 * nfp + 1], ah[mf], bl2 + 2);
                }
            }
        }

        const int n0 = nbase + nn * BNS;
        #pragma unroll
        for (int mf = 0; mf < MF; mf++) {
            const int row = m0 + wm + mf * 16 + (lane >> 2);
            #pragma unroll
            for (int nf = 0; nf < NF; nf++) {
                const int col = n0 + wn + nf * 8 + (lane & 3) * 2;
                float2 v0 = { acc[mf][nf][0] * scale, acc[mf][nf][1] * scale };
                float2 v1 = { acc[mf][nf][2] * scale, acc[mf][nf][3] * scale };
                *(float2*)&C[(size_t)row * Sn + col] = v0;
                *(float2*)&C[(size_t)(row + 8) * Sn + col] = v1;
            }
        }

        if (hasNext) {
            cvtB((nn + 1) & 1);
            __syncthreads();
        }
    }
}

// ============================ aux kernels ============================
struct RopeB { const float* src[4]; float* dst[4]; };
__global__ void rope_b(RopeB rb) {
    const int i = blockIdx.x * 256 + threadIdx.x;
    const float* Y = rb.src[blockIdx.y];
    float* Qr = rb.dst[blockIdx.y];
    const int j = i & 31;
    const int s = (i >> 5) & (Sn - 1);
    const int bh = i >> 16;
    const int b = bh >> 4, h = bh & 15;
    const float* yr = Y + ((size_t)(b * Sn + s)) * En + h * 64;
    const float x1 = yr[j], x2 = yr[j + 32];
    const double invf = pow(10000.0, -(double)j / 32.0);
    const float ang = (float)((double)s * invf);
    const float sv = sinf(ang), cv = cosf(ang);
    float* o = Qr + ((size_t)bh * Sn + s) * 64;
    o[j]      = x1 * cv - x2 * sv;
    o[j + 32] = x1 * sv + x2 * cv;
}

struct VtB { const float* src[2]; float* dst[2]; };
__global__ void vtrans_b(VtB vb) {
    __shared__ float t[64][65];
    const int task = blockIdx.z >> 5;
    const int bh = blockIdx.z & 31;
    const float* Yv = vb.src[task];
    float* VT = vb.dst[task];
    const int s0 = blockIdx.x * 64;
    const int b = bh >> 4, h = bh & 15;
    const int tid = threadIdx.x;
    #pragma unroll
    for (int i = 0; i < 16; i++) {
        const int u = i * 256 + tid;
        const int s = u >> 6, d = u & 63;
        t[s][d] = Yv[((size_t)(b * Sn + s0 + s)) * En + h * 64 + d];
    }
    __syncthreads();
    #pragma unroll
    for (int i = 0; i < 16; i++) {
        const int u = i * 256 + tid;
        const int d = u >> 6, s = u & 63;
        VT[((size_t)bh * 64 + d) * Sn + s0 + s] = t[s][d];
    }
}

__global__ void softmax_b(float* __restrict__ wa, float* __restrict__ wb) {
    float* W = blockIdx.y ? wb : wa;
    const int row = blockIdx.x;
    const int q = row & (Sn - 1);
    float* p = W + (size_t)row * Sn;
    const int tid = threadIdx.x;
    const int c0 = tid * 4, c1 = 1024 + tid * 4;
    __shared__ float red[8];

    const float4 z4 = { 0.f, 0.f, 0.f, 0.f };
    float4 a = (c0 <= q) ? *(float4*)(p + c0) : z4;
    float4 b = (c1 <= q) ? *(float4*)(p + c1) : z4;
    float v[8] = { a.x, a.y, a.z, a.w, b.x, b.y, b.z, b.w };

    float m = -1e30f;
    #pragma unroll
    for (int j = 0; j < 8; j++) {
        const int col = (j < 4) ? (c0 + j) : (c1 + j - 4);
        if (col <= q) m = fmaxf(m, v[j]);
    }
    #pragma unroll
    for (int o = 16; o; o >>= 1) m = fmaxf(m, __shfl_xor_sync(0xffffffffu, m, o));
    if ((tid & 31) == 0) red[tid >> 5] = m;
    __syncthreads();
    if (tid < 32) {
        float mm = (tid < 8) ? red[tid] : -1e30f;
        #pragma unroll
        for (int o = 4; o; o >>= 1) mm = fmaxf(mm, __shfl_xor_sync(0xffffffffu, mm, o));
        if (tid == 0) red[0] = mm;
    }
    __syncthreads();
    m = red[0];
    __syncthreads();

    float sum = 0.f;
    #pragma unroll
    for (int j = 0; j < 8; j++) {
        const int col = (j < 4) ? (c0 + j) : (c1 + j - 4);
        v[j] = (col <= q) ? expf(v[j] - m) : 0.f;
        sum += v[j];
    }
    #pragma unroll
    for (int o = 16; o; o >>= 1) sum += __shfl_xor_sync(0xffffffffu, sum, o);
    if ((tid & 31) == 0) red[tid >> 5] = sum;
    __syncthreads();
    if (tid < 32) {
        float s = (tid < 8) ? red[tid] : 0.f;
        #pragma unroll
        for (int o = 4; o; o >>= 1) s += __shfl_xor_sync(0xffffffffu, s, o);
        if (tid == 0) red[0] = s;
    }
    __syncthreads();
    const float inv = 1.0f / red[0];

    a.x = v[0] * inv; a.y = v[1] * inv; a.z = v[2] * inv; a.w = v[3] * inv;
    b.x = v[4] * inv; b.y = v[5] * inv; b.z = v[6] * inv; b.w = v[7] * inv;
    *(float4*)(p + c0) = a;
    *(float4*)(p + c1) = b;
}

// ============================ launch ============================
extern "C" void kernel_launch(void* const* d_in, const int* in_sizes, int n_in,
                              void* d_out, int out_size) {
    const float* query = (const float*)d_in[0];
    const float* key   = (const float*)d_in[1];
    const float* value = (const float*)d_in[2];
    // d_in[3] = mask (causal tril, hardcoded)
    const float* Wf[7] = {
        (const float*)d_in[4],  (const float*)d_in[5], (const float*)d_in[6],
        (const float*)d_in[7],  (const float*)d_in[8], (const float*)d_in[9],
        (const float*)d_in[10]
    };

    float* out = (float*)d_out;
    float* w1  = out + (size_t)M_ROWS * En;
    float* w2  = w1 + WSZ;

    unsigned char* sc = nullptr;
    cudaGetSymbolAddress((void**)&sc, g_scratch);

    float* Y[6];
    for (int i = 0; i < 6; i++) Y[i] = (float*)(sc + (size_t)(16 * i) * MBb);
    float* QK[4];
    for (int i = 0; i < 4; i++) QK[i] = (float*)(sc + (size_t)(96 + 16 * i) * MBb);
    float* VT[2];
    for (int i = 0; i < 2; i++) VT[i] = (float*)(sc + (size_t)(160 + 16 * i) * MBb);
    float* CC[2];
    for (int i = 0; i < 2; i++) CC[i] = (float*)(sc + (size_t)(192 + 16 * i) * MBb);

    const int SMEM_128 = (2 * 128 + 2 * 128) * 72 * 2 * 2; // 147456
    const int SMEM_64  = (2 * 128 + 2 * 64) * 72 * 2 * 2;  // 110592
    const int SMEM_SC  = (2 * 128 + 4 * 128) * 72 * 2;     // 110592
    cudaFuncSetAttribute((const void*)&gemm2<128, 0, 0>,
                         cudaFuncAttributeMaxDynamicSharedMemorySize, SMEM_128);
    cudaFuncSetAttribute((const void*)&gemm2<128, 0, 1>,
                         cudaFuncAttributeMaxDynamicSharedMemorySize, SMEM_128);
    cudaFuncSetAttribute((const void*)&gemm2<64, 2, 0>,
                         cudaFuncAttributeMaxDynamicSharedMemorySize, SMEM_64);
    cudaFuncSetAttribute((const void*)&scores_nl<4>,
                         cudaFuncAttributeMaxDynamicSharedMemorySize, SMEM_SC);

    // 1) six projections, one launch
    PtrBatch bp = {};
    bp.A[0] = query; bp.A[1] = key; bp.A[2] = value;
    bp.A[3] = query; bp.A[4] = key; bp.A[5] = value;
    for (int i = 0; i < 6; i++) { bp.B[i] = Wf[i]; bp.C[i] = Y[i]; }
    gemm2<128, 0, 0><<<dim3(En / 128, M_ROWS / 128, 6), 512, SMEM_128>>>(
        bp, 0, 0, 0, 0, En, En, En, En, 1.f);

    // 2) rope (4 tensors) + V transpose (2 tensors)
    RopeB rb = {};
    rb.src[0] = Y[0]; rb.dst[0] = QK[0];
    rb.src[1] = Y[1]; rb.dst[1] = QK[1];
    rb.src[2] = Y[3]; rb.dst[2] = QK[2];
    rb.src[3] = Y[4]; rb.dst[3] = QK[3];
    rope_b<<<dim3((Bn * Hn * Sn * 32) / 256, 4), 256>>>(rb);
    VtB vb = {};
    vb.src[0] = Y[2]; vb.dst[0] = VT[0];
    vb.src[1] = Y[5]; vb.dst[1] = VT[1];
    vtrans_b<<<dim3(Sn / 64, 1, 64), 256>>>(vb);

    // 3) scores both heads: NSUB=4
    PtrBatch bs = {};
    bs.A[0] = QK[0]; bs.B[0] = QK[1]; bs.C[0] = w1;
    bs.A[1] = QK[2]; bs.B[1] = QK[3]; bs.C[1] = w2;
    scores_nl<4><<<dim3(Sn / 512, Sn / 128, 64), 512, SMEM_SC>>>(bs, 0.125f);

    // 4) softmax both heads
    softmax_b<<<dim3(Bn * Hn * Sn, 2), 256>>>(w1, w2);

    // 5) ctx both heads, causal kmax
    PtrBatch bc = {};
    bc.A[0] = w1; bc.B[0] = VT[0]; bc.C[0] = CC[0];
    bc.A[1] = w2; bc.B[1] = VT[1]; bc.C[1] = CC[1];
    gemm2<64, 2, 0><<<dim3(1, Sn / 128, 64), 512, SMEM_64>>>(
        bc, 5, (long long)Sn * Sn, (long long)64 * Sn, (long long)Sn * 64,
        Sn, Sn, 64, Sn, 1.f);

    // 6) output projection with fused ctx1*ctx2 A-load
    PtrBatch bo = {};
    bo.A[0] = CC[0]; bo.A2[0] = CC[1]; bo.B[0] = Wf[6]; bo.C[0] = out;
    gemm2<128, 0, 1><<<dim3(En / 128, M_ROWS / 128, 1), 512, SMEM_128>>>(
        bo, 0, 0, 0, 0, En, En, En, En, 1.f);
}